// round 9
// baseline (speedup 1.0000x reference)
#include <cuda_runtime.h>
#include <cuda_bf16.h>
#include <cstdint>

#define D_MODEL 1024
#define KV_DIM 256
#define N_HEADS 16
#define HEAD_DIM 64
#define TSEQ 2048
#define BATCH 2
#define BT (BATCH * TSEQ)
#define KH2 (D_MODEL / 2)   // packed-u32 row stride for K=1024

// Scratch (device globals; no allocation anywhere).
__device__ float g_Q[(size_t)BT * D_MODEL];
__device__ float g_K[(size_t)BT * KV_DIM];
__device__ float g_V[(size_t)BT * KV_DIM];
// packed bf16x2 hi/lo operands
__device__ uint32_t g_xh[(size_t)BT * KH2];
__device__ uint32_t g_xl[(size_t)BT * KH2];
__device__ uint32_t g_Oh[(size_t)BT * KH2];
__device__ uint32_t g_Ol[(size_t)BT * KH2];
__device__ uint32_t g_WqTh[(size_t)D_MODEL * KH2];
__device__ uint32_t g_WqTl[(size_t)D_MODEL * KH2];
__device__ uint32_t g_WkTh[(size_t)KV_DIM * KH2];
__device__ uint32_t g_WkTl[(size_t)KV_DIM * KH2];
__device__ uint32_t g_WvTh[(size_t)KV_DIM * KH2];
__device__ uint32_t g_WvTl[(size_t)KV_DIM * KH2];
__device__ uint32_t g_WoTh[(size_t)D_MODEL * KH2];
__device__ uint32_t g_WoTl[(size_t)D_MODEL * KH2];

// ---------------------------------------------------------------------------
// Helpers
// ---------------------------------------------------------------------------
__device__ __forceinline__ float f2tf32(float v) {
    uint32_t u; asm("cvt.rna.tf32.f32 %0, %1;" : "=r"(u) : "f"(v));
    return __uint_as_float(u);
}

__device__ __forceinline__ void mma1688(float* d, float a0, float a1, float a2,
                                        float a3, float b0, float b1) {
    asm volatile(
        "mma.sync.aligned.m16n8k8.row.col.f32.tf32.tf32.f32 "
        "{%0,%1,%2,%3}, {%4,%5,%6,%7}, {%8,%9}, {%0,%1,%2,%3};"
        : "+f"(d[0]), "+f"(d[1]), "+f"(d[2]), "+f"(d[3])
        : "r"(__float_as_uint(a0)), "r"(__float_as_uint(a1)),
          "r"(__float_as_uint(a2)), "r"(__float_as_uint(a3)),
          "r"(__float_as_uint(b0)), "r"(__float_as_uint(b1)));
}

__device__ __forceinline__ void mma16816(float* d, uint32_t a0, uint32_t a1,
                                         uint32_t a2, uint32_t a3,
                                         uint32_t b0, uint32_t b1) {
    asm volatile(
        "mma.sync.aligned.m16n8k16.row.col.f32.bf16.bf16.f32 "
        "{%0,%1,%2,%3}, {%4,%5,%6,%7}, {%8,%9}, {%0,%1,%2,%3};"
        : "+f"(d[0]), "+f"(d[1]), "+f"(d[2]), "+f"(d[3])
        : "r"(a0), "r"(a1), "r"(a2), "r"(a3), "r"(b0), "r"(b1));
}

__device__ __forceinline__ uint32_t packbf(__nv_bfloat16 a, __nv_bfloat16 b) {
    __nv_bfloat162 t(a, b);   // a -> low 16 bits
    return *reinterpret_cast<uint32_t*>(&t);
}

__device__ __forceinline__ uint32_t smem_u32p(const void* p) {
    uint32_t r;
    asm("{ .reg .u64 t; cvta.to.shared.u64 t, %1; cvt.u32.u64 %0, t; }"
        : "=r"(r) : "l"(p));
    return r;
}

__device__ __forceinline__ void cp16(uint32_t dst, const void* src) {
    asm volatile("cp.async.cg.shared.global [%0], [%1], 16;"
                 :: "r"(dst), "l"(src));
}
#define CP_COMMIT() asm volatile("cp.async.commit_group;" ::: "memory")
#define CP_WAIT0()  asm volatile("cp.async.wait_group 0;" ::: "memory")

// ---------------------------------------------------------------------------
// One-shot converters
// ---------------------------------------------------------------------------
__global__ __launch_bounds__(256) void conv_pack(
    const float* __restrict__ A, uint32_t* __restrict__ H,
    uint32_t* __restrict__ L, int n4)
{
    int i = blockIdx.x * blockDim.x + threadIdx.x;
    if (i >= n4) return;
    float4 v = ((const float4*)A)[i];
    __nv_bfloat16 hx = __float2bfloat16_rn(v.x);
    __nv_bfloat16 hy = __float2bfloat16_rn(v.y);
    __nv_bfloat16 hz = __float2bfloat16_rn(v.z);
    __nv_bfloat16 hw = __float2bfloat16_rn(v.w);
    ((uint2*)H)[i] = make_uint2(packbf(hx, hy), packbf(hz, hw));
    ((uint2*)L)[i] = make_uint2(
        packbf(__float2bfloat16_rn(v.x - __bfloat162float(hx)),
               __float2bfloat16_rn(v.y - __bfloat162float(hy))),
        packbf(__float2bfloat16_rn(v.z - __bfloat162float(hz)),
               __float2bfloat16_rn(v.w - __bfloat162float(hw))));
}

// All 4 weight transposes in ONE launch: z selects the matrix.
__global__ __launch_bounds__(256) void conv_wT_all(
    const float* __restrict__ Wq, const float* __restrict__ Wk,
    const float* __restrict__ Wv, const float* __restrict__ Wo)
{
    const float* W; uint32_t* H; uint32_t* L; int N;
    switch (blockIdx.z) {
        case 0: W = Wq; H = g_WqTh; L = g_WqTl; N = D_MODEL; break;
        case 1: W = Wk; H = g_WkTh; L = g_WkTl; N = KV_DIM;  break;
        case 2: W = Wv; H = g_WvTh; L = g_WvTl; N = KV_DIM;  break;
        default:W = Wo; H = g_WoTh; L = g_WoTl; N = D_MODEL; break;
    }
    const int n0 = blockIdx.x * 32, k0 = blockIdx.y * 32;
    if (n0 >= N) return;
    __shared__ float t[32][33];
    const int tx = threadIdx.x, ty = threadIdx.y;
#pragma unroll
    for (int i = 0; i < 4; i++)
        t[ty + i * 8][tx] = W[(size_t)(k0 + ty + i * 8) * N + n0 + tx];
    __syncthreads();
#pragma unroll
    for (int i = 0; i < 2; i++) {
        const int kp = ty + i * 8;
        float a = t[kp * 2][tx], b = t[kp * 2 + 1][tx];
        __nv_bfloat16 ha = __float2bfloat16_rn(a);
        __nv_bfloat16 hb = __float2bfloat16_rn(b);
        const size_t o = (size_t)(n0 + tx) * KH2 + k0 / 2 + kp;
        H[o] = packbf(ha, hb);
        L[o] = packbf(__float2bfloat16_rn(a - __bfloat162float(ha)),
                      __float2bfloat16_rn(b - __bfloat162float(hb)));
    }
}

// ---------------------------------------------------------------------------
// 2-term bf16-split GEMM on packed operands, cp.async double-buffered (R8).
// ---------------------------------------------------------------------------
#define GROW 20
#define G_AH 0
#define G_AL (128 * GROW)
#define G_BH (2 * 128 * GROW)
#define G_BL (3 * 128 * GROW)
#define G_U32 (4 * 128 * GROW)
#define GEMM_SMEM (2 * G_U32 * 4)

__device__ __forceinline__ void gemm_stage(
    uint32_t sbase, const uint32_t* __restrict__ AH,
    const uint32_t* __restrict__ AL, const uint32_t* __restrict__ BH,
    const uint32_t* __restrict__ BL, int KH, int m0, int n0, int kc2)
{
    const int tid = threadIdx.x;
#pragma unroll
    for (int j = 0; j < 2; j++) {
        const int idx = tid + j * 256;
        const int r = idx >> 2, sg = (idx & 3) * 4;
        const size_t ao = (size_t)(m0 + r) * KH + kc2 + sg;
        const size_t bo = (size_t)(n0 + r) * KH + kc2 + sg;
        const uint32_t d = sbase + (r * GROW + sg) * 4;
        cp16(d + G_AH * 4, AH + ao);
        cp16(d + G_AL * 4, AL + ao);
        cp16(d + G_BH * 4, BH + bo);
        cp16(d + G_BL * 4, BL + bo);
    }
    CP_COMMIT();
}

__device__ __forceinline__ void gemm_tile_pk(
    const uint32_t* __restrict__ AH, const uint32_t* __restrict__ AL,
    const uint32_t* __restrict__ BH, const uint32_t* __restrict__ BL,
    const float* __restrict__ bias, float* __restrict__ C,
    int N, int KH, int m0, int n0)
{
    extern __shared__ uint32_t su[];
    const uint32_t sbase = smem_u32p(su);

    const int tid = threadIdx.x;
    const int lane = tid & 31;
    const int wid = tid >> 5;
    const int wm = (wid >> 2) * 64;
    const int wn = (wid & 3) * 32;
    const int lr = lane >> 2;
    const int lc = lane & 3;

    float acc[4][4][4];
#pragma unroll
    for (int i = 0; i < 4; i++)
#pragma unroll
        for (int j = 0; j < 4; j++)
#pragma unroll
            for (int k = 0; k < 4; k++) acc[i][j][k] = 0.0f;

    const int NC = KH / 16;
    int buf = 0;

    gemm_stage(sbase, AH, AL, BH, BL, KH, m0, n0, 0);

    for (int c = 0; c < NC; c++) {
        CP_WAIT0();
        __syncthreads();
        if (c + 1 < NC)
            gemm_stage(sbase + (buf ^ 1) * G_U32 * 4,
                       AH, AL, BH, BL, KH, m0, n0, (c + 1) * 16);

        const uint32_t* sb = su + buf * G_U32;
#pragma unroll
        for (int ss = 0; ss < 2; ss++) {
            const int kp = ss * 8 + lc;
            uint32_t bh[4][2], bl[4][2];
#pragma unroll
            for (int nt = 0; nt < 4; nt++) {
                const int n = wn + nt * 8 + lr;
                bh[nt][0] = sb[G_BH + n * GROW + kp];
                bh[nt][1] = sb[G_BH + n * GROW + kp + 4];
                bl[nt][0] = sb[G_BL + n * GROW + kp];
                bl[nt][1] = sb[G_BL + n * GROW + kp + 4];
            }
#pragma unroll
            for (int mt = 0; mt < 4; mt++) {
                const int m = wm + mt * 16 + lr;
                uint32_t ah0 = sb[G_AH + m * GROW + kp];
                uint32_t ah1 = sb[G_AH + (m + 8) * GROW + kp];
                uint32_t ah2 = sb[G_AH + m * GROW + kp + 4];
                uint32_t ah3 = sb[G_AH + (m + 8) * GROW + kp + 4];
                uint32_t al0 = sb[G_AL + m * GROW + kp];
                uint32_t al1 = sb[G_AL + (m + 8) * GROW + kp];
                uint32_t al2 = sb[G_AL + m * GROW + kp + 4];
                uint32_t al3 = sb[G_AL + (m + 8) * GROW + kp + 4];
#pragma unroll
                for (int nt = 0; nt < 4; nt++) {
                    mma16816(acc[mt][nt], ah0, ah1, ah2, ah3, bh[nt][0], bh[nt][1]);
                    mma16816(acc[mt][nt], ah0, ah1, ah2, ah3, bl[nt][0], bl[nt][1]);
                    mma16816(acc[mt][nt], al0, al1, al2, al3, bh[nt][0], bh[nt][1]);
                }
            }
        }
        buf ^= 1;
    }

#pragma unroll
    for (int nt = 0; nt < 4; nt++) {
        const int n = n0 + wn + nt * 8 + lc * 2;
        const float2 bv = *(const float2*)(bias + n);
#pragma unroll
        for (int mt = 0; mt < 4; mt++) {
            const int m = m0 + wm + mt * 16 + lr;
            float2 o0 = make_float2(acc[mt][nt][0] + bv.x, acc[mt][nt][1] + bv.y);
            float2 o1 = make_float2(acc[mt][nt][2] + bv.x, acc[mt][nt][3] + bv.y);
            *(float2*)(C + (size_t)m * N + n) = o0;
            *(float2*)(C + (size_t)(m + 8) * N + n) = o1;
        }
    }
}

__global__ __launch_bounds__(256, 2) void gemm_qkv(
    const float* __restrict__ bq, const float* __restrict__ bk,
    const float* __restrict__ bv,
    float* __restrict__ Q, float* __restrict__ K, float* __restrict__ V)
{
    const int col0 = blockIdx.x * 128;
    const int m0 = blockIdx.y * 128;
    if (col0 < D_MODEL) {
        gemm_tile_pk(g_xh, g_xl, g_WqTh, g_WqTl, bq, Q, D_MODEL, KH2, m0, col0);
    } else if (col0 < D_MODEL + KV_DIM) {
        gemm_tile_pk(g_xh, g_xl, g_WkTh, g_WkTl, bk, K, KV_DIM, KH2, m0, col0 - D_MODEL);
    } else {
        gemm_tile_pk(g_xh, g_xl, g_WvTh, g_WvTl, bv, V, KV_DIM, KH2, m0,
                     col0 - D_MODEL - KV_DIM);
    }
}

__global__ __launch_bounds__(256, 2) void gemm_o(
    const float* __restrict__ bias, float* __restrict__ C)
{
    gemm_tile_pk(g_Oh, g_Ol, g_WoTh, g_WoTl, bias, C, D_MODEL, KH2,
                 blockIdx.y * 128, blockIdx.x * 128);
}

// ---------------------------------------------------------------------------
// Causal GQA flash attention (tf32 mma.sync), cp.async-pipelined K/V staging,
// hoisted Q fragments, exp2-domain softmax.
// smem: [Kraw|Vraw] aliases Qs (dead after prologue); Ks, Vt, Ps.
// ---------------------------------------------------------------------------
#define AT_ST 68
#define OFF_KS (128 * AT_ST)
#define OFF_VT (192 * AT_ST)
#define OFF_PS (256 * AT_ST)
#define OFF_VRAW (64 * AT_ST)
#define ATTN_SMEM (384 * AT_ST * 4)

__global__ __launch_bounds__(256) void attn_mma()
{
    extern __shared__ float sm[];
    float* Qs   = sm;                  // prologue only
    float* Kraw = sm;                  // aliases Qs after prologue
    float* Vraw = sm + OFF_VRAW;
    float* Ks   = sm + OFF_KS;
    float* Vt   = sm + OFF_VT;
    float* Ps   = sm + OFF_PS;
    const uint32_t sbase = smem_u32p(sm);

    const int tid = threadIdx.x;
    const int lane = tid & 31;
    const int w = tid >> 5;
    const int lr = lane >> 2;
    const int lc = lane & 3;
    const int qt = blockIdx.x, h = blockIdx.y, b = blockIdx.z;
    const int g = h >> 2;
    const int tb = b * TSEQ;
    const float sc2 = 0.125f * 1.4426950408889634f;  // scale * log2(e)

    // Stage Q (scaled to log2 domain, tf32-rounded).
    {
        const int r = tid >> 1, c0 = (tid & 1) * 32;
        const float* qr = g_Q + (size_t)(tb + qt * 128 + r) * D_MODEL + h * HEAD_DIM + c0;
        float* dst = Qs + r * AT_ST + c0;
#pragma unroll
        for (int i = 0; i < 8; i++) {
            float4 v = *(const float4*)(qr + i * 4);
            v.x = f2tf32(v.x * sc2); v.y = f2tf32(v.y * sc2);
            v.z = f2tf32(v.z * sc2); v.w = f2tf32(v.w * sc2);
            *(float4*)(dst + i * 4) = v;
        }
    }
    __syncthreads();

    const int r0 = w * 16 + lr;
    // Hoist Q fragments (loop-invariant).
    float qf[8][4];
#pragma unroll
    for (int kb8 = 0; kb8 < 8; kb8++) {
        const float* q0 = Qs + r0 * AT_ST + kb8 * 8 + lc;
        qf[kb8][0] = q0[0];
        qf[kb8][1] = q0[8 * AT_ST];
        qf[kb8][2] = q0[4];
        qf[kb8][3] = q0[8 * AT_ST + 4];
    }
    __syncthreads();   // Qs now dead; Kraw/Vraw may be written

    const int sr = tid >> 2, sc0 = (tid & 3) * 16;   // staging assignment
    const float* kbase = g_K + (size_t)tb * KV_DIM + g * HEAD_DIM;
    const float* vbase = g_V + (size_t)tb * KV_DIM + g * HEAD_DIM;

    const int nkt = 2 * qt + 2;

    // Issue cp.async for kt=0.
    {
        const float* kr = kbase + (size_t)sr * KV_DIM + sc0;
        const float* vr = vbase + (size_t)sr * KV_DIM + sc0;
        const uint32_t d = sbase + (sr * AT_ST + sc0) * 4;
#pragma unroll
        for (int i = 0; i < 4; i++) {
            cp16(d + i * 16, kr + i * 4);
            cp16(d + OFF_VRAW * 4 + i * 16, vr + i * 4);
        }
        CP_COMMIT();
    }

    float oacc[8][4];
#pragma unroll
    for (int nt = 0; nt < 8; nt++)
#pragma unroll
        for (int j = 0; j < 4; j++) oacc[nt][j] = 0.0f;
    float m0 = -1e30f, m1 = -1e30f, l0 = 0.0f, l1 = 0.0f;

    const int qi0 = qt * 128 + r0;
    const int qi1 = qi0 + 8;

    for (int kt = 0; kt < nkt; kt++) {
        CP_WAIT0();
        __syncthreads();   // raw ready; prior compute done (Ks/Vt writable)

        // Convert pass: Kraw -> Ks (tf32), Vraw -> Vt (tf32, transposed).
#pragma unroll
        for (int i = 0; i < 4; i++) {
            float4 v = *(const float4*)(Kraw + sr * AT_ST + sc0 + i * 4);
            v.x = f2tf32(v.x); v.y = f2tf32(v.y);
            v.z = f2tf32(v.z); v.w = f2tf32(v.w);
            *(float4*)(Ks + sr * AT_ST + sc0 + i * 4) = v;
        }
#pragma unroll
        for (int i = 0; i < 4; i++) {
            float4 v = *(const float4*)(Vraw + sr * AT_ST + sc0 + i * 4);
            Vt[(sc0 + i * 4 + 0) * AT_ST + sr] = f2tf32(v.x);
            Vt[(sc0 + i * 4 + 1) * AT_ST + sr] = f2tf32(v.y);
            Vt[(sc0 + i * 4 + 2) * AT_ST + sr] = f2tf32(v.z);
            Vt[(sc0 + i * 4 + 3) * AT_ST + sr] = f2tf32(v.w);
        }
        __syncthreads();   // Ks/Vt ready; Kraw/Vraw free

        // Prefetch next tile during compute.
        if (kt + 1 < nkt) {
            const float* kr = kbase + (size_t)((kt + 1) * 64 + sr) * KV_DIM + sc0;
            const float* vr = vbase + (size_t)((kt + 1) * 64 + sr) * KV_DIM + sc0;
            const uint32_t d = sbase + (sr * AT_ST + sc0) * 4;
#pragma unroll
            for (int i = 0; i < 4; i++) {
                cp16(d + i * 16, kr + i * 4);
                cp16(d + OFF_VRAW * 4 + i * 16, vr + i * 4);
            }
            CP_COMMIT();
        }

        // S = Q @ K^T
        float sa[8][4];
#pragma unroll
        for (int nt = 0; nt < 8; nt++)
#pragma unroll
            for (int j = 0; j < 4; j++) sa[nt][j] = 0.0f;
#pragma unroll
        for (int kb8 = 0; kb8 < 8; kb8++) {
            const float a0 = qf[kb8][0], a1 = qf[kb8][1];
            const float a2 = qf[kb8][2], a3 = qf[kb8][3];
            const int kb = kb8 * 8;
#pragma unroll
            for (int nt = 0; nt < 8; nt++) {
                const float* kk = Ks + (nt * 8 + lr) * AT_ST + kb + lc;
                mma1688(sa[nt], a0, a1, a2, a3, kk[0], kk[4]);
            }
        }

        if (kt >= 2 * qt) {
#pragma unroll
            for (int nt = 0; nt < 8; nt++) {
                const int kj = kt * 64 + nt * 8 + 2 * lc;
                if (kj > qi0)     sa[nt][0] = -1e30f;
                if (kj + 1 > qi0) sa[nt][1] = -1e30f;
                if (kj > qi1)     sa[nt][2] = -1e30f;
                if (kj + 1 > qi1) sa[nt][3] = -1e30f;
            }
        }

        // Online softmax in log2 domain.
        float mx0 = sa[0][0], mx1 = sa[0][2];
#pragma unroll
        for (int nt = 0; nt < 8; nt++) {
            mx0 = fmaxf(mx0, fmaxf(sa[nt][0], sa[nt][1]));
            mx1 = fmaxf(mx1, fmaxf(sa[nt][2], sa[nt][3]));
        }
        mx0 = fmaxf(mx0, __shfl_xor_sync(0xffffffffu, mx0, 1));
        mx0 = fmaxf(mx0, __shfl_xor_sync(0xffffffffu, mx0, 2));
        mx1 = fmaxf(mx1, __shfl_xor_sync(0xffffffffu, mx1, 1));
        mx1 = fmaxf(mx1, __shfl_xor_sync(0xffffffffu, mx1, 2));
        const float nm0 = fmaxf(m0, mx0), nm1 = fmaxf(m1, mx1);
        const float cf0 = exp2f(m0 - nm0), cf1 = exp2f(m1 - nm1);
        m0 = nm0; m1 = nm1;
        float rs0 = 0.0f, rs1 = 0.0f;
#pragma unroll
        for (int nt = 0; nt < 8; nt++) {
            float p0 = exp2f(sa[nt][0] - nm0);
            float p1 = exp2f(sa[nt][1] - nm0);
            float p2 = exp2f(sa[nt][2] - nm1);
            float p3 = exp2f(sa[nt][3] - nm1);
            rs0 += p0 + p1; rs1 += p2 + p3;
            sa[nt][0] = f2tf32(p0); sa[nt][1] = f2tf32(p1);
            sa[nt][2] = f2tf32(p2); sa[nt][3] = f2tf32(p3);
        }
        rs0 += __shfl_xor_sync(0xffffffffu, rs0, 1);
        rs0 += __shfl_xor_sync(0xffffffffu, rs0, 2);
        rs1 += __shfl_xor_sync(0xffffffffu, rs1, 1);
        rs1 += __shfl_xor_sync(0xffffffffu, rs1, 2);
        l0 = l0 * cf0 + rs0;
        l1 = l1 * cf1 + rs1;
#pragma unroll
        for (int nt = 0; nt < 8; nt++) {
            oacc[nt][0] *= cf0; oacc[nt][1] *= cf0;
            oacc[nt][2] *= cf1; oacc[nt][3] *= cf1;
        }

        // P -> smem (warp-local), then O += P @ V.
#pragma unroll
        for (int nt = 0; nt < 8; nt++) {
            *(float2*)(Ps + r0 * AT_ST + nt * 8 + 2 * lc) =
                make_float2(sa[nt][0], sa[nt][1]);
            *(float2*)(Ps + (r0 + 8) * AT_ST + nt * 8 + 2 * lc) =
                make_float2(sa[nt][2], sa[nt][3]);
        }
        __syncwarp();

#pragma unroll
        for (int kb = 0; kb < 64; kb += 8) {
            const float* pr = Ps + r0 * AT_ST + kb + lc;
            const float a0 = pr[0];
            const float a1 = pr[8 * AT_ST];
            const float a2 = pr[4];
            const float a3 = pr[8 * AT_ST + 4];
#pragma unroll
            for (int nt = 0; nt < 8; nt++) {
                const float* vv = Vt + (nt * 8 + lr) * AT_ST + kb + lc;
                mma1688(oacc[nt], a0, a1, a2, a3, vv[0], vv[4]);
            }
        }
        __syncwarp();
    }

    // Normalize; write packed bf16x2 hi/lo (feeds gemm_o).
    const float inv0 = 1.0f / l0, inv1 = 1.0f / l1;
    const size_t row0 = (size_t)(tb + qt * 128 + r0);
    const int colp = h * 32 + lc;
#pragma unroll
    for (int nt = 0; nt < 8; nt++) {
        float v0 = oacc[nt][0] * inv0, v1 = oacc[nt][1] * inv0;
        float v2 = oacc[nt][2] * inv1, v3 = oacc[nt][3] * inv1;
        __nv_bfloat16 h0 = __float2bfloat16_rn(v0);
        __nv_bfloat16 h1 = __float2bfloat16_rn(v1);
        __nv_bfloat16 h2 = __float2bfloat16_rn(v2);
        __nv_bfloat16 h3 = __float2bfloat16_rn(v3);
        const size_t o0 = row0 * KH2 + colp + nt * 4;
        const size_t o1 = (row0 + 8) * KH2 + colp + nt * 4;
        g_Oh[o0] = packbf(h0, h1);
        g_Ol[o0] = packbf(__float2bfloat16_rn(v0 - __bfloat162float(h0)),
                          __float2bfloat16_rn(v1 - __bfloat162float(h1)));
        g_Oh[o1] = packbf(h2, h3);
        g_Ol[o1] = packbf(__float2bfloat16_rn(v2 - __bfloat162float(h2)),
                          __float2bfloat16_rn(v3 - __bfloat162float(h3)));
    }
}

// ---------------------------------------------------------------------------
extern "C" void kernel_launch(void* const* d_in, const int* in_sizes, int n_in,
                              void* d_out, int out_size)
{
    const float* x  = (const float*)d_in[0];
    const float* Wq = (const float*)d_in[1];
    const float* bq = (const float*)d_in[2];
    const float* Wk = (const float*)d_in[3];
    const float* bk = (const float*)d_in[4];
    const float* Wv = (const float*)d_in[5];
    const float* bv = (const float*)d_in[6];
    const float* Wo = (const float*)d_in[7];
    const float* bo = (const float*)d_in[8];
    float* out = (float*)d_out;

    float *Qp, *Kp, *Vp;
    uint32_t *xh, *xl;
    cudaGetSymbolAddress((void**)&Qp, g_Q);
    cudaGetSymbolAddress((void**)&Kp, g_K);
    cudaGetSymbolAddress((void**)&Vp, g_V);
    cudaGetSymbolAddress((void**)&xh, g_xh);
    cudaGetSymbolAddress((void**)&xl, g_xl);

    cudaFuncSetAttribute(gemm_qkv, cudaFuncAttributeMaxDynamicSharedMemorySize, GEMM_SMEM);
    cudaFuncSetAttribute(gemm_o,   cudaFuncAttributeMaxDynamicSharedMemorySize, GEMM_SMEM);
    cudaFuncSetAttribute(attn_mma, cudaFuncAttributeMaxDynamicSharedMemorySize, ATTN_SMEM);

    // One-shot conversions (weights in a single launch).
    conv_pack<<<(BT * D_MODEL / 4 + 255) / 256, 256>>>(x, xh, xl, BT * D_MODEL / 4);
    conv_wT_all<<<dim3(D_MODEL / 32, D_MODEL / 32, 4), dim3(32, 8)>>>(Wq, Wk, Wv, Wo);

    // Fused QKV projection.
    gemm_qkv<<<dim3((D_MODEL + 2 * KV_DIM) / 128, BT / 128), 256, GEMM_SMEM>>>(
        bq, bk, bv, Qp, Kp, Vp);

    // Causal GQA attention (writes packed hi/lo output).
    attn_mma<<<dim3(TSEQ / 128, N_HEADS, BATCH), 256, ATTN_SMEM>>>();

    // Output projection.
    gemm_o<<<dim3(D_MODEL / 128, BT / 128), 256, GEMM_SMEM>>>(bo, out);
}

// round 10
// speedup vs baseline: 1.2558x; 1.2558x over previous
#include <cuda_runtime.h>
#include <cuda_bf16.h>
#include <cstdint>

#define D_MODEL 1024
#define KV_DIM 256
#define N_HEADS 16
#define HEAD_DIM 64
#define TSEQ 2048
#define BATCH 2
#define BT (BATCH * TSEQ)
#define KH2 (D_MODEL / 2)   // packed-u32 row stride for K=1024
#define QSCALE (0.125f * 1.4426950408889634f)   // 1/sqrt(64) * log2(e)

// Scratch (device globals; no allocation anywhere).
__device__ float g_Q[(size_t)BT * D_MODEL];
__device__ float g_K[(size_t)BT * KV_DIM];
__device__ float g_V[(size_t)BT * KV_DIM];
// packed bf16x2 hi/lo operands
__device__ uint32_t g_xh[(size_t)BT * KH2];
__device__ uint32_t g_xl[(size_t)BT * KH2];
__device__ uint32_t g_Oh[(size_t)BT * KH2];
__device__ uint32_t g_Ol[(size_t)BT * KH2];
__device__ uint32_t g_WqTh[(size_t)D_MODEL * KH2];
__device__ uint32_t g_WqTl[(size_t)D_MODEL * KH2];
__device__ uint32_t g_WkTh[(size_t)KV_DIM * KH2];
__device__ uint32_t g_WkTl[(size_t)KV_DIM * KH2];
__device__ uint32_t g_WvTh[(size_t)KV_DIM * KH2];
__device__ uint32_t g_WvTl[(size_t)KV_DIM * KH2];
__device__ uint32_t g_WoTh[(size_t)D_MODEL * KH2];
__device__ uint32_t g_WoTl[(size_t)D_MODEL * KH2];

// ---------------------------------------------------------------------------
// Helpers
// ---------------------------------------------------------------------------
__device__ __forceinline__ float f2tf32(float v) {
    uint32_t u; asm("cvt.rna.tf32.f32 %0, %1;" : "=r"(u) : "f"(v));
    return __uint_as_float(u);
}

__device__ __forceinline__ void mma1688(float* d, float a0, float a1, float a2,
                                        float a3, float b0, float b1) {
    asm volatile(
        "mma.sync.aligned.m16n8k8.row.col.f32.tf32.tf32.f32 "
        "{%0,%1,%2,%3}, {%4,%5,%6,%7}, {%8,%9}, {%0,%1,%2,%3};"
        : "+f"(d[0]), "+f"(d[1]), "+f"(d[2]), "+f"(d[3])
        : "r"(__float_as_uint(a0)), "r"(__float_as_uint(a1)),
          "r"(__float_as_uint(a2)), "r"(__float_as_uint(a3)),
          "r"(__float_as_uint(b0)), "r"(__float_as_uint(b1)));
}

__device__ __forceinline__ void mma16816(float* d, uint32_t a0, uint32_t a1,
                                         uint32_t a2, uint32_t a3,
                                         uint32_t b0, uint32_t b1) {
    asm volatile(
        "mma.sync.aligned.m16n8k16.row.col.f32.bf16.bf16.f32 "
        "{%0,%1,%2,%3}, {%4,%5,%6,%7}, {%8,%9}, {%0,%1,%2,%3};"
        : "+f"(d[0]), "+f"(d[1]), "+f"(d[2]), "+f"(d[3])
        : "r"(a0), "r"(a1), "r"(a2), "r"(a3), "r"(b0), "r"(b1));
}

__device__ __forceinline__ uint32_t packbf(__nv_bfloat16 a, __nv_bfloat16 b) {
    __nv_bfloat162 t(a, b);   // a -> low 16 bits
    return *reinterpret_cast<uint32_t*>(&t);
}

__device__ __forceinline__ uint32_t smem_u32p(const void* p) {
    uint32_t r;
    asm("{ .reg .u64 t; cvta.to.shared.u64 t, %1; cvt.u32.u64 %0, t; }"
        : "=r"(r) : "l"(p));
    return r;
}

__device__ __forceinline__ void cp16(uint32_t dst, const void* src) {
    asm volatile("cp.async.cg.shared.global [%0], [%1], 16;"
                 :: "r"(dst), "l"(src));
}
#define CP_COMMIT() asm volatile("cp.async.commit_group;" ::: "memory")
#define CP_WAIT0()  asm volatile("cp.async.wait_group 0;" ::: "memory")
#define CP_WAIT1()  asm volatile("cp.async.wait_group 1;" ::: "memory")
#define CP_WAIT2()  asm volatile("cp.async.wait_group 2;" ::: "memory")

// ---------------------------------------------------------------------------
// One-shot converters
// ---------------------------------------------------------------------------
__global__ __launch_bounds__(256) void conv_pack(
    const float* __restrict__ A, uint32_t* __restrict__ H,
    uint32_t* __restrict__ L, int n4)
{
    int i = blockIdx.x * blockDim.x + threadIdx.x;
    if (i >= n4) return;
    float4 v = ((const float4*)A)[i];
    __nv_bfloat16 hx = __float2bfloat16_rn(v.x);
    __nv_bfloat16 hy = __float2bfloat16_rn(v.y);
    __nv_bfloat16 hz = __float2bfloat16_rn(v.z);
    __nv_bfloat16 hw = __float2bfloat16_rn(v.w);
    ((uint2*)H)[i] = make_uint2(packbf(hx, hy), packbf(hz, hw));
    ((uint2*)L)[i] = make_uint2(
        packbf(__float2bfloat16_rn(v.x - __bfloat162float(hx)),
               __float2bfloat16_rn(v.y - __bfloat162float(hy))),
        packbf(__float2bfloat16_rn(v.z - __bfloat162float(hz)),
               __float2bfloat16_rn(v.w - __bfloat162float(hw))));
}

// All 4 weight transposes in ONE launch: z selects the matrix.
__global__ __launch_bounds__(256) void conv_wT_all(
    const float* __restrict__ Wq, const float* __restrict__ Wk,
    const float* __restrict__ Wv, const float* __restrict__ Wo)
{
    const float* W; uint32_t* H; uint32_t* L; int N;
    switch (blockIdx.z) {
        case 0: W = Wq; H = g_WqTh; L = g_WqTl; N = D_MODEL; break;
        case 1: W = Wk; H = g_WkTh; L = g_WkTl; N = KV_DIM;  break;
        case 2: W = Wv; H = g_WvTh; L = g_WvTl; N = KV_DIM;  break;
        default:W = Wo; H = g_WoTh; L = g_WoTl; N = D_MODEL; break;
    }
    const int n0 = blockIdx.x * 32, k0 = blockIdx.y * 32;
    if (n0 >= N) return;
    __shared__ float t[32][33];
    const int tx = threadIdx.x, ty = threadIdx.y;
#pragma unroll
    for (int i = 0; i < 4; i++)
        t[ty + i * 8][tx] = W[(size_t)(k0 + ty + i * 8) * N + n0 + tx];
    __syncthreads();
#pragma unroll
    for (int i = 0; i < 2; i++) {
        const int kp = ty + i * 8;
        float a = t[kp * 2][tx], b = t[kp * 2 + 1][tx];
        __nv_bfloat16 ha = __float2bfloat16_rn(a);
        __nv_bfloat16 hb = __float2bfloat16_rn(b);
        const size_t o = (size_t)(n0 + tx) * KH2 + k0 / 2 + kp;
        H[o] = packbf(ha, hb);
        L[o] = packbf(__float2bfloat16_rn(a - __bfloat162float(ha)),
                      __float2bfloat16_rn(b - __bfloat162float(hb)));
    }
}

// ---------------------------------------------------------------------------
// 2-term bf16-split GEMM on packed operands, cp.async double-buffered.
// TF32OUT: round output to tf32 (RNA) after premul — used for Q/K/V, which
// feed only the tf32 attention MMAs (moves attn's convert pass here for free).
// ---------------------------------------------------------------------------
#define GROW 20
#define G_AH 0
#define G_AL (128 * GROW)
#define G_BH (2 * 128 * GROW)
#define G_BL (3 * 128 * GROW)
#define G_U32 (4 * 128 * GROW)
#define GEMM_SMEM (2 * G_U32 * 4)

__device__ __forceinline__ void gemm_stage(
    uint32_t sbase, const uint32_t* __restrict__ AH,
    const uint32_t* __restrict__ AL, const uint32_t* __restrict__ BH,
    const uint32_t* __restrict__ BL, int KH, int m0, int n0, int kc2)
{
    const int tid = threadIdx.x;
#pragma unroll
    for (int j = 0; j < 2; j++) {
        const int idx = tid + j * 256;
        const int r = idx >> 2, sg = (idx & 3) * 4;
        const size_t ao = (size_t)(m0 + r) * KH + kc2 + sg;
        const size_t bo = (size_t)(n0 + r) * KH + kc2 + sg;
        const uint32_t d = sbase + (r * GROW + sg) * 4;
        cp16(d + G_AH * 4, AH + ao);
        cp16(d + G_AL * 4, AL + ao);
        cp16(d + G_BH * 4, BH + bo);
        cp16(d + G_BL * 4, BL + bo);
    }
    CP_COMMIT();
}

template <bool TF32OUT>
__device__ __forceinline__ void gemm_tile_pk(
    const uint32_t* __restrict__ AH, const uint32_t* __restrict__ AL,
    const uint32_t* __restrict__ BH, const uint32_t* __restrict__ BL,
    const float* __restrict__ bias, float* __restrict__ C,
    int N, int KH, int m0, int n0, float premul)
{
    extern __shared__ uint32_t su[];
    const uint32_t sbase = smem_u32p(su);

    const int tid = threadIdx.x;
    const int lane = tid & 31;
    const int wid = tid >> 5;
    const int wm = (wid >> 2) * 64;
    const int wn = (wid & 3) * 32;
    const int lr = lane >> 2;
    const int lc = lane & 3;

    float acc[4][4][4];
#pragma unroll
    for (int i = 0; i < 4; i++)
#pragma unroll
        for (int j = 0; j < 4; j++)
#pragma unroll
            for (int k = 0; k < 4; k++) acc[i][j][k] = 0.0f;

    const int NC = KH / 16;
    int buf = 0;

    gemm_stage(sbase, AH, AL, BH, BL, KH, m0, n0, 0);

    for (int c = 0; c < NC; c++) {
        CP_WAIT0();
        __syncthreads();
        if (c + 1 < NC)
            gemm_stage(sbase + (buf ^ 1) * G_U32 * 4,
                       AH, AL, BH, BL, KH, m0, n0, (c + 1) * 16);

        const uint32_t* sb = su + buf * G_U32;
#pragma unroll
        for (int ss = 0; ss < 2; ss++) {
            const int kp = ss * 8 + lc;
            uint32_t bh[4][2], bl[4][2];
#pragma unroll
            for (int nt = 0; nt < 4; nt++) {
                const int n = wn + nt * 8 + lr;
                bh[nt][0] = sb[G_BH + n * GROW + kp];
                bh[nt][1] = sb[G_BH + n * GROW + kp + 4];
                bl[nt][0] = sb[G_BL + n * GROW + kp];
                bl[nt][1] = sb[G_BL + n * GROW + kp + 4];
            }
#pragma unroll
            for (int mt = 0; mt < 4; mt++) {
                const int m = wm + mt * 16 + lr;
                uint32_t ah0 = sb[G_AH + m * GROW + kp];
                uint32_t ah1 = sb[G_AH + (m + 8) * GROW + kp];
                uint32_t ah2 = sb[G_AH + m * GROW + kp + 4];
                uint32_t ah3 = sb[G_AH + (m + 8) * GROW + kp + 4];
                uint32_t al0 = sb[G_AL + m * GROW + kp];
                uint32_t al1 = sb[G_AL + (m + 8) * GROW + kp];
                uint32_t al2 = sb[G_AL + m * GROW + kp + 4];
                uint32_t al3 = sb[G_AL + (m + 8) * GROW + kp + 4];
#pragma unroll
                for (int nt = 0; nt < 4; nt++) {
                    mma16816(acc[mt][nt], ah0, ah1, ah2, ah3, bh[nt][0], bh[nt][1]);
                    mma16816(acc[mt][nt], ah0, ah1, ah2, ah3, bl[nt][0], bl[nt][1]);
                    mma16816(acc[mt][nt], al0, al1, al2, al3, bh[nt][0], bh[nt][1]);
                }
            }
        }
        buf ^= 1;
    }

#pragma unroll
    for (int nt = 0; nt < 4; nt++) {
        const int n = n0 + wn + nt * 8 + lc * 2;
        const float2 bv = *(const float2*)(bias + n);
#pragma unroll
        for (int mt = 0; mt < 4; mt++) {
            const int m = m0 + wm + mt * 16 + lr;
            float2 o0, o1;
            if (TF32OUT) {
                o0 = make_float2(f2tf32((acc[mt][nt][0] + bv.x) * premul),
                                 f2tf32((acc[mt][nt][1] + bv.y) * premul));
                o1 = make_float2(f2tf32((acc[mt][nt][2] + bv.x) * premul),
                                 f2tf32((acc[mt][nt][3] + bv.y) * premul));
            } else {
                o0 = make_float2(acc[mt][nt][0] + bv.x, acc[mt][nt][1] + bv.y);
                o1 = make_float2(acc[mt][nt][2] + bv.x, acc[mt][nt][3] + bv.y);
            }
            *(float2*)(C + (size_t)m * N + n) = o0;
            *(float2*)(C + (size_t)(m + 8) * N + n) = o1;
        }
    }
}

__global__ __launch_bounds__(256, 2) void gemm_qkv(
    const float* __restrict__ bq, const float* __restrict__ bk,
    const float* __restrict__ bv,
    float* __restrict__ Q, float* __restrict__ K, float* __restrict__ V)
{
    const int col0 = blockIdx.x * 128;
    const int m0 = blockIdx.y * 128;
    if (col0 < D_MODEL) {
        gemm_tile_pk<true>(g_xh, g_xl, g_WqTh, g_WqTl, bq, Q, D_MODEL, KH2,
                           m0, col0, QSCALE);
    } else if (col0 < D_MODEL + KV_DIM) {
        gemm_tile_pk<true>(g_xh, g_xl, g_WkTh, g_WkTl, bk, K, KV_DIM, KH2,
                           m0, col0 - D_MODEL, 1.0f);
    } else {
        gemm_tile_pk<true>(g_xh, g_xl, g_WvTh, g_WvTl, bv, V, KV_DIM, KH2,
                           m0, col0 - D_MODEL - KV_DIM, 1.0f);
    }
}

__global__ __launch_bounds__(256, 2) void gemm_o(
    const float* __restrict__ bias, float* __restrict__ C)
{
    gemm_tile_pk<false>(g_Oh, g_Ol, g_WoTh, g_WoTl, bias, C, D_MODEL, KH2,
                        blockIdx.y * 128, blockIdx.x * 128, 1.0f);
}

// ---------------------------------------------------------------------------
// Causal GQA flash attention (tf32 mma.sync).
// - Q/K/V arrive pre-rounded (Q pre-scaled) from gemm_qkv: no convert pass.
// - cp.async double-buffered Ks (stride 68) and row-major Vs (stride 72:
//   direct conflict-free B-fragment reads, no transpose).
// - Balanced: grid.x=8, each CTA runs q-tiles (15-bx) then bx = 34 iters.
// ---------------------------------------------------------------------------
#define PS_ST 68
#define KS_ST 68
#define VS_ST 72
#define OFF_KS (128 * PS_ST)            // 8704 floats
#define KS_BUF (64 * KS_ST)             // 4352
#define OFF_VS (OFF_KS + 2 * KS_BUF)    // 17408
#define VS_BUF (64 * VS_ST)             // 4608
#define ATTN_SMEM ((OFF_VS + 2 * VS_BUF) * 4)   // 106496 B

__global__ __launch_bounds__(256, 2) void attn_mma()
{
    extern __shared__ float sm[];
    const uint32_t sbase = smem_u32p(sm);
    float* Ps = sm;                     // also Q staging region

    const int tid = threadIdx.x;
    const int lane = tid & 31;
    const int w = tid >> 5;
    const int lr = lane >> 2;
    const int lc = lane & 3;
    const int bx = blockIdx.x, h = blockIdx.y, b = blockIdx.z;
    const int g = h >> 2;
    const int tb = b * TSEQ;
    const int r0 = w * 16 + lr;
    const int sr = tid >> 2, sc0 = (tid & 3) * 16;
    const float* kbase = g_K + (size_t)tb * KV_DIM + g * HEAD_DIM;
    const float* vbase = g_V + (size_t)tb * KV_DIM + g * HEAD_DIM;

    auto stage_kv = [&](int kt) {
        const int buf = kt & 1;
        const float* kr = kbase + (size_t)(kt * 64 + sr) * KV_DIM + sc0;
        const float* vr = vbase + (size_t)(kt * 64 + sr) * KV_DIM + sc0;
        const uint32_t kd = sbase + (OFF_KS + buf * KS_BUF + sr * KS_ST + sc0) * 4;
        const uint32_t vd = sbase + (OFF_VS + buf * VS_BUF + sr * VS_ST + sc0) * 4;
#pragma unroll
        for (int i = 0; i < 4; i++) {
            cp16(kd + i * 16, kr + i * 4);
            cp16(vd + i * 16, vr + i * 4);
        }
        CP_COMMIT();
    };

    for (int pass = 0; pass < 2; pass++) {
        const int qt = pass ? bx : (TSEQ / 128 - 1 - bx);
        const int nkt = 2 * qt + 2;

        __syncthreads();   // previous pass fully done with all smem regions

        // Q tile via cp.async (pre-scaled, pre-rounded by gemm_qkv).
        {
            const int r = tid >> 1, c0 = (tid & 1) * 32;
            const float* qr = g_Q + (size_t)(tb + qt * 128 + r) * D_MODEL
                              + h * HEAD_DIM + c0;
            const uint32_t d = sbase + (r * PS_ST + c0) * 4;
#pragma unroll
            for (int i = 0; i < 8; i++) cp16(d + i * 16, qr + i * 4);
            CP_COMMIT();
        }
        stage_kv(0);
        stage_kv(1);       // nkt >= 2 always
        CP_WAIT2();        // Q landed (kt0/kt1 may still be in flight)
        __syncthreads();

        // Hoist Q fragments (loop-invariant).
        float qf[8][4];
#pragma unroll
        for (int kb8 = 0; kb8 < 8; kb8++) {
            const float* q0 = Ps + r0 * PS_ST + kb8 * 8 + lc;
            qf[kb8][0] = q0[0];
            qf[kb8][1] = q0[8 * PS_ST];
            qf[kb8][2] = q0[4];
            qf[kb8][3] = q0[8 * PS_ST + 4];
        }

        float oacc[8][4];
#pragma unroll
        for (int nt = 0; nt < 8; nt++)
#pragma unroll
            for (int j = 0; j < 4; j++) oacc[nt][j] = 0.0f;
        float m0 = -1e30f, m1 = -1e30f, l0 = 0.0f, l1 = 0.0f;

        const int qi0 = qt * 128 + r0;
        const int qi1 = qi0 + 8;

        for (int kt = 0; kt < nkt; kt++) {
            if (kt + 1 < nkt) { CP_WAIT1(); } else { CP_WAIT0(); }
            __syncthreads();
            const float* Ks = sm + OFF_KS + (kt & 1) * KS_BUF;
            const float* Vs = sm + OFF_VS + (kt & 1) * VS_BUF;

            // S = Q @ K^T
            float sa[8][4];
#pragma unroll
            for (int nt = 0; nt < 8; nt++)
#pragma unroll
                for (int j = 0; j < 4; j++) sa[nt][j] = 0.0f;
#pragma unroll
            for (int kb8 = 0; kb8 < 8; kb8++) {
                const float a0 = qf[kb8][0], a1 = qf[kb8][1];
                const float a2 = qf[kb8][2], a3 = qf[kb8][3];
                const int kb = kb8 * 8;
#pragma unroll
                for (int nt = 0; nt < 8; nt++) {
                    const float* kk = Ks + (nt * 8 + lr) * KS_ST + kb + lc;
                    mma1688(sa[nt], a0, a1, a2, a3, kk[0], kk[4]);
                }
            }

            if (kt >= 2 * qt) {
#pragma unroll
                for (int nt = 0; nt < 8; nt++) {
                    const int kj = kt * 64 + nt * 8 + 2 * lc;
                    if (kj > qi0)     sa[nt][0] = -1e30f;
                    if (kj + 1 > qi0) sa[nt][1] = -1e30f;
                    if (kj > qi1)     sa[nt][2] = -1e30f;
                    if (kj + 1 > qi1) sa[nt][3] = -1e30f;
                }
            }

            // Online softmax (log2 domain; logits pre-scaled in Q).
            float mx0 = sa[0][0], mx1 = sa[0][2];
#pragma unroll
            for (int nt = 0; nt < 8; nt++) {
                mx0 = fmaxf(mx0, fmaxf(sa[nt][0], sa[nt][1]));
                mx1 = fmaxf(mx1, fmaxf(sa[nt][2], sa[nt][3]));
            }
            mx0 = fmaxf(mx0, __shfl_xor_sync(0xffffffffu, mx0, 1));
            mx0 = fmaxf(mx0, __shfl_xor_sync(0xffffffffu, mx0, 2));
            mx1 = fmaxf(mx1, __shfl_xor_sync(0xffffffffu, mx1, 1));
            mx1 = fmaxf(mx1, __shfl_xor_sync(0xffffffffu, mx1, 2));
            const float nm0 = fmaxf(m0, mx0), nm1 = fmaxf(m1, mx1);
            const float cf0 = exp2f(m0 - nm0), cf1 = exp2f(m1 - nm1);
            m0 = nm0; m1 = nm1;
            float rs0 = 0.0f, rs1 = 0.0f;
#pragma unroll
            for (int nt = 0; nt < 8; nt++) {
                float p0 = exp2f(sa[nt][0] - nm0);
                float p1 = exp2f(sa[nt][1] - nm0);
                float p2 = exp2f(sa[nt][2] - nm1);
                float p3 = exp2f(sa[nt][3] - nm1);
                rs0 += p0 + p1; rs1 += p2 + p3;
                sa[nt][0] = f2tf32(p0); sa[nt][1] = f2tf32(p1);
                sa[nt][2] = f2tf32(p2); sa[nt][3] = f2tf32(p3);
            }
            rs0 += __shfl_xor_sync(0xffffffffu, rs0, 1);
            rs0 += __shfl_xor_sync(0xffffffffu, rs0, 2);
            rs1 += __shfl_xor_sync(0xffffffffu, rs1, 1);
            rs1 += __shfl_xor_sync(0xffffffffu, rs1, 2);
            l0 = l0 * cf0 + rs0;
            l1 = l1 * cf1 + rs1;
#pragma unroll
            for (int nt = 0; nt < 8; nt++) {
                oacc[nt][0] *= cf0; oacc[nt][1] *= cf0;
                oacc[nt][2] *= cf1; oacc[nt][3] *= cf1;
            }

            // P -> smem (warp-local rows), then O += P @ V (V read direct).
#pragma unroll
            for (int nt = 0; nt < 8; nt++) {
                *(float2*)(Ps + r0 * PS_ST + nt * 8 + 2 * lc) =
                    make_float2(sa[nt][0], sa[nt][1]);
                *(float2*)(Ps + (r0 + 8) * PS_ST + nt * 8 + 2 * lc) =
                    make_float2(sa[nt][2], sa[nt][3]);
            }
            __syncwarp();

#pragma unroll
            for (int kb = 0; kb < 64; kb += 8) {
                const float* pr = Ps + r0 * PS_ST + kb + lc;
                const float a0 = pr[0];
                const float a1 = pr[8 * PS_ST];
                const float a2 = pr[4];
                const float a3 = pr[8 * PS_ST + 4];
#pragma unroll
                for (int nt = 0; nt < 8; nt++) {
                    const float b0 = Vs[(kb + lc) * VS_ST + nt * 8 + lr];
                    const float b1 = Vs[(kb + lc + 4) * VS_ST + nt * 8 + lr];
                    mma1688(oacc[nt], a0, a1, a2, a3, b0, b1);
                }
            }
            __syncthreads();            // all reads of this buffer done
            if (kt + 2 < nkt) stage_kv(kt + 2);
        }

        // Normalize; write packed bf16x2 hi/lo (feeds gemm_o).
        const float inv0 = 1.0f / l0, inv1 = 1.0f / l1;
        const size_t row0 = (size_t)(tb + qt * 128 + r0);
        const int colp = h * 32 + lc;
#pragma unroll
        for (int nt = 0; nt < 8; nt++) {
            float v0 = oacc[nt][0] * inv0, v1 = oacc[nt][1] * inv0;
            float v2 = oacc[nt][2] * inv1, v3 = oacc[nt][3] * inv1;
            __nv_bfloat16 h0 = __float2bfloat16_rn(v0);
            __nv_bfloat16 h1 = __float2bfloat16_rn(v1);
            __nv_bfloat16 h2 = __float2bfloat16_rn(v2);
            __nv_bfloat16 h3 = __float2bfloat16_rn(v3);
            const size_t o0 = row0 * KH2 + colp + nt * 4;
            const size_t o1 = (row0 + 8) * KH2 + colp + nt * 4;
            g_Oh[o0] = packbf(h0, h1);
            g_Ol[o0] = packbf(__float2bfloat16_rn(v0 - __bfloat162float(h0)),
                              __float2bfloat16_rn(v1 - __bfloat162float(h1)));
            g_Oh[o1] = packbf(h2, h3);
            g_Ol[o1] = packbf(__float2bfloat16_rn(v2 - __bfloat162float(h2)),
                              __float2bfloat16_rn(v3 - __bfloat162float(h3)));
        }
    }
}

// ---------------------------------------------------------------------------
extern "C" void kernel_launch(void* const* d_in, const int* in_sizes, int n_in,
                              void* d_out, int out_size)
{
    const float* x  = (const float*)d_in[0];
    const float* Wq = (const float*)d_in[1];
    const float* bq = (const float*)d_in[2];
    const float* Wk = (const float*)d_in[3];
    const float* bk = (const float*)d_in[4];
    const float* Wv = (const float*)d_in[5];
    const float* bv = (const float*)d_in[6];
    const float* Wo = (const float*)d_in[7];
    const float* bo = (const float*)d_in[8];
    float* out = (float*)d_out;

    float *Qp, *Kp, *Vp;
    uint32_t *xh, *xl;
    cudaGetSymbolAddress((void**)&Qp, g_Q);
    cudaGetSymbolAddress((void**)&Kp, g_K);
    cudaGetSymbolAddress((void**)&Vp, g_V);
    cudaGetSymbolAddress((void**)&xh, g_xh);
    cudaGetSymbolAddress((void**)&xl, g_xl);

    cudaFuncSetAttribute(gemm_qkv, cudaFuncAttributeMaxDynamicSharedMemorySize, GEMM_SMEM);
    cudaFuncSetAttribute(gemm_o,   cudaFuncAttributeMaxDynamicSharedMemorySize, GEMM_SMEM);
    cudaFuncSetAttribute(attn_mma, cudaFuncAttributeMaxDynamicSharedMemorySize, ATTN_SMEM);

    // One-shot conversions.
    conv_pack<<<(BT * D_MODEL / 4 + 255) / 256, 256>>>(x, xh, xl, BT * D_MODEL / 4);
    conv_wT_all<<<dim3(D_MODEL / 32, D_MODEL / 32, 4), dim3(32, 8)>>>(Wq, Wk, Wv, Wo);

    // Fused QKV projection (Q pre-scaled + tf32-rounded; K/V tf32-rounded).
    gemm_qkv<<<dim3((D_MODEL + 2 * KV_DIM) / 128, BT / 128), 256, GEMM_SMEM>>>(
        bq, bk, bv, Qp, Kp, Vp);

    // Causal GQA attention (balanced two-tile CTAs; writes packed hi/lo).
    attn_mma<<<dim3(TSEQ / 256, N_HEADS, BATCH), 256, ATTN_SMEM>>>();

    // Output projection.
    gemm_o<<<dim3(D_MODEL / 128, BT / 128), 256, GEMM_SMEM>>>(bo, out);
}

// round 11
// speedup vs baseline: 1.3156x; 1.0476x over previous
#include <cuda_runtime.h>
#include <cuda_bf16.h>
#include <cstdint>

#define D_MODEL 1024
#define KV_DIM 256
#define N_HEADS 16
#define HEAD_DIM 64
#define TSEQ 2048
#define BATCH 2
#define BT (BATCH * TSEQ)
#define KH2 (D_MODEL / 2)
#define QSCALE (0.125f * 1.4426950408889634f)   // 1/sqrt(64) * log2(e)
#define N_JOBS (16 * N_HEADS * BATCH)           // 512 attention tile-jobs

// Scratch (device globals; no allocation anywhere).
__device__ float g_Q[(size_t)BT * D_MODEL];
__device__ float g_K[(size_t)BT * KV_DIM];
__device__ float g_V[(size_t)BT * KV_DIM];
__device__ int g_jobctr;
// packed bf16x2 hi/lo operands
__device__ uint32_t g_xh[(size_t)BT * KH2];
__device__ uint32_t g_xl[(size_t)BT * KH2];
__device__ uint32_t g_Oh[(size_t)BT * KH2];
__device__ uint32_t g_Ol[(size_t)BT * KH2];
__device__ uint32_t g_WqTh[(size_t)D_MODEL * KH2];
__device__ uint32_t g_WqTl[(size_t)D_MODEL * KH2];
__device__ uint32_t g_WkTh[(size_t)KV_DIM * KH2];
__device__ uint32_t g_WkTl[(size_t)KV_DIM * KH2];
__device__ uint32_t g_WvTh[(size_t)KV_DIM * KH2];
__device__ uint32_t g_WvTl[(size_t)KV_DIM * KH2];
__device__ uint32_t g_WoTh[(size_t)D_MODEL * KH2];
__device__ uint32_t g_WoTl[(size_t)D_MODEL * KH2];

// ---------------------------------------------------------------------------
// Helpers
// ---------------------------------------------------------------------------
__device__ __forceinline__ float f2tf32(float v) {
    uint32_t u; asm("cvt.rna.tf32.f32 %0, %1;" : "=r"(u) : "f"(v));
    return __uint_as_float(u);
}

__device__ __forceinline__ void mma1688(float* d, float a0, float a1, float a2,
                                        float a3, float b0, float b1) {
    asm volatile(
        "mma.sync.aligned.m16n8k8.row.col.f32.tf32.tf32.f32 "
        "{%0,%1,%2,%3}, {%4,%5,%6,%7}, {%8,%9}, {%0,%1,%2,%3};"
        : "+f"(d[0]), "+f"(d[1]), "+f"(d[2]), "+f"(d[3])
        : "r"(__float_as_uint(a0)), "r"(__float_as_uint(a1)),
          "r"(__float_as_uint(a2)), "r"(__float_as_uint(a3)),
          "r"(__float_as_uint(b0)), "r"(__float_as_uint(b1)));
}

__device__ __forceinline__ void mma16816(float* d, uint32_t a0, uint32_t a1,
                                         uint32_t a2, uint32_t a3,
                                         uint32_t b0, uint32_t b1) {
    asm volatile(
        "mma.sync.aligned.m16n8k16.row.col.f32.bf16.bf16.f32 "
        "{%0,%1,%2,%3}, {%4,%5,%6,%7}, {%8,%9}, {%0,%1,%2,%3};"
        : "+f"(d[0]), "+f"(d[1]), "+f"(d[2]), "+f"(d[3])
        : "r"(a0), "r"(a1), "r"(a2), "r"(a3), "r"(b0), "r"(b1));
}

__device__ __forceinline__ void ldsm4(uint32_t& r0, uint32_t& r1,
                                      uint32_t& r2, uint32_t& r3, uint32_t a) {
    asm volatile("ldmatrix.sync.aligned.m8n8.x4.shared.b16 {%0,%1,%2,%3}, [%4];"
                 : "=r"(r0), "=r"(r1), "=r"(r2), "=r"(r3) : "r"(a));
}

__device__ __forceinline__ uint32_t packbf(__nv_bfloat16 a, __nv_bfloat16 b) {
    __nv_bfloat162 t(a, b);
    return *reinterpret_cast<uint32_t*>(&t);
}

__device__ __forceinline__ uint32_t smem_u32p(const void* p) {
    uint32_t r;
    asm("{ .reg .u64 t; cvta.to.shared.u64 t, %1; cvt.u32.u64 %0, t; }"
        : "=r"(r) : "l"(p));
    return r;
}

__device__ __forceinline__ void cp16(uint32_t dst, const void* src) {
    asm volatile("cp.async.cg.shared.global [%0], [%1], 16;"
                 :: "r"(dst), "l"(src));
}
#define CP_COMMIT() asm volatile("cp.async.commit_group;" ::: "memory")
#define CP_WAIT0()  asm volatile("cp.async.wait_group 0;" ::: "memory")
#define CP_WAIT1()  asm volatile("cp.async.wait_group 1;" ::: "memory")
#define CP_WAIT2()  asm volatile("cp.async.wait_group 2;" ::: "memory")

// ---------------------------------------------------------------------------
// One-shot converters
// ---------------------------------------------------------------------------
__global__ __launch_bounds__(256) void conv_pack(
    const float* __restrict__ A, uint32_t* __restrict__ H,
    uint32_t* __restrict__ L, int n4)
{
    int i = blockIdx.x * blockDim.x + threadIdx.x;
    if (i >= n4) return;
    float4 v = ((const float4*)A)[i];
    __nv_bfloat16 hx = __float2bfloat16_rn(v.x);
    __nv_bfloat16 hy = __float2bfloat16_rn(v.y);
    __nv_bfloat16 hz = __float2bfloat16_rn(v.z);
    __nv_bfloat16 hw = __float2bfloat16_rn(v.w);
    ((uint2*)H)[i] = make_uint2(packbf(hx, hy), packbf(hz, hw));
    ((uint2*)L)[i] = make_uint2(
        packbf(__float2bfloat16_rn(v.x - __bfloat162float(hx)),
               __float2bfloat16_rn(v.y - __bfloat162float(hy))),
        packbf(__float2bfloat16_rn(v.z - __bfloat162float(hz)),
               __float2bfloat16_rn(v.w - __bfloat162float(hw))));
}

__global__ __launch_bounds__(256) void conv_wT_all(
    const float* __restrict__ Wq, const float* __restrict__ Wk,
    const float* __restrict__ Wv, const float* __restrict__ Wo)
{
    const float* W; uint32_t* H; uint32_t* L; int N;
    switch (blockIdx.z) {
        case 0: W = Wq; H = g_WqTh; L = g_WqTl; N = D_MODEL; break;
        case 1: W = Wk; H = g_WkTh; L = g_WkTl; N = KV_DIM;  break;
        case 2: W = Wv; H = g_WvTh; L = g_WvTl; N = KV_DIM;  break;
        default:W = Wo; H = g_WoTh; L = g_WoTl; N = D_MODEL; break;
    }
    const int n0 = blockIdx.x * 32, k0 = blockIdx.y * 32;
    if (n0 >= N) return;
    __shared__ float t[32][33];
    const int tx = threadIdx.x, ty = threadIdx.y;
#pragma unroll
    for (int i = 0; i < 4; i++)
        t[ty + i * 8][tx] = W[(size_t)(k0 + ty + i * 8) * N + n0 + tx];
    __syncthreads();
#pragma unroll
    for (int i = 0; i < 2; i++) {
        const int kp = ty + i * 8;
        float a = t[kp * 2][tx], b = t[kp * 2 + 1][tx];
        __nv_bfloat16 ha = __float2bfloat16_rn(a);
        __nv_bfloat16 hb = __float2bfloat16_rn(b);
        const size_t o = (size_t)(n0 + tx) * KH2 + k0 / 2 + kp;
        H[o] = packbf(ha, hb);
        L[o] = packbf(__float2bfloat16_rn(a - __bfloat162float(ha)),
                      __float2bfloat16_rn(b - __bfloat162float(hb)));
    }
}

__global__ void reset_ctr() { if (threadIdx.x == 0) g_jobctr = 0; }

// ---------------------------------------------------------------------------
// 2-term bf16-split GEMM, cp.async double-buffered, ldmatrix fragment loads.
// ---------------------------------------------------------------------------
#define GROW 20
#define G_AH 0
#define G_AL (128 * GROW)
#define G_BH (2 * 128 * GROW)
#define G_BL (3 * 128 * GROW)
#define G_U32 (4 * 128 * GROW)
#define GEMM_SMEM (2 * G_U32 * 4)

__device__ __forceinline__ void gemm_stage(
    uint32_t sbase, const uint32_t* __restrict__ AH,
    const uint32_t* __restrict__ AL, const uint32_t* __restrict__ BH,
    const uint32_t* __restrict__ BL, int KH, int m0, int n0, int kc2)
{
    const int tid = threadIdx.x;
#pragma unroll
    for (int j = 0; j < 2; j++) {
        const int idx = tid + j * 256;
        const int r = idx >> 2, sg = (idx & 3) * 4;
        const size_t ao = (size_t)(m0 + r) * KH + kc2 + sg;
        const size_t bo = (size_t)(n0 + r) * KH + kc2 + sg;
        const uint32_t d = sbase + (r * GROW + sg) * 4;
        cp16(d + G_AH * 4, AH + ao);
        cp16(d + G_AL * 4, AL + ao);
        cp16(d + G_BH * 4, BH + bo);
        cp16(d + G_BL * 4, BL + bo);
    }
    CP_COMMIT();
}

template <bool TF32OUT>
__device__ __forceinline__ void gemm_tile_pk(
    const uint32_t* __restrict__ AH, const uint32_t* __restrict__ AL,
    const uint32_t* __restrict__ BH, const uint32_t* __restrict__ BL,
    const float* __restrict__ bias, float* __restrict__ C,
    int N, int KH, int m0, int n0, float premul)
{
    extern __shared__ uint32_t su[];
    const uint32_t sbase = smem_u32p(su);

    const int tid = threadIdx.x;
    const int lane = tid & 31;
    const int wid = tid >> 5;
    const int wm = (wid >> 2) * 64;
    const int wn = (wid & 3) * 32;
    const int lr = lane >> 2;
    const int lc = lane & 3;
    const int lt = lane >> 3;          // ldmatrix tile id 0..3
    const int lrr = lane & 7;          // ldmatrix row within tile

    // Per-lane ldmatrix base addresses (bytes).
    const uint32_t aBase = sbase +
        (((wm + (lt & 1) * 8 + lrr) * GROW + (lt >> 1) * 4) << 2);
    const uint32_t bBase = sbase +
        ((G_BH + (wn + (lt >> 1) * 8 + lrr) * GROW + (lt & 1) * 4) << 2);

    float acc[4][4][4];
#pragma unroll
    for (int i = 0; i < 4; i++)
#pragma unroll
        for (int j = 0; j < 4; j++)
#pragma unroll
            for (int k = 0; k < 4; k++) acc[i][j][k] = 0.0f;

    const int NC = KH / 16;
    int buf = 0;

    gemm_stage(sbase, AH, AL, BH, BL, KH, m0, n0, 0);

    for (int c = 0; c < NC; c++) {
        CP_WAIT0();
        __syncthreads();
        if (c + 1 < NC)
            gemm_stage(sbase + (buf ^ 1) * G_U32 * 4,
                       AH, AL, BH, BL, KH, m0, n0, (c + 1) * 16);

        const uint32_t bufo = (uint32_t)buf * G_U32 * 4;
#pragma unroll
        for (int ss = 0; ss < 2; ss++) {
            uint32_t bh[4][2], bl[4][2];
#pragma unroll
            for (int p = 0; p < 2; p++) {
                const uint32_t off = bufo + ((p * 16 * GROW + ss * 8) << 2);
                ldsm4(bh[2 * p][0], bh[2 * p][1], bh[2 * p + 1][0],
                      bh[2 * p + 1][1], bBase + off);
                ldsm4(bl[2 * p][0], bl[2 * p][1], bl[2 * p + 1][0],
                      bl[2 * p + 1][1], bBase + off + ((128 * GROW) << 2));
            }
#pragma unroll
            for (int mt = 0; mt < 4; mt++) {
                const uint32_t off = bufo + ((mt * 16 * GROW + ss * 8) << 2);
                uint32_t ah0, ah1, ah2, ah3, al0, al1, al2, al3;
                ldsm4(ah0, ah1, ah2, ah3, aBase + off);
                ldsm4(al0, al1, al2, al3, aBase + off + ((G_AL) << 2));
#pragma unroll
                for (int nt = 0; nt < 4; nt++) {
                    mma16816(acc[mt][nt], ah0, ah1, ah2, ah3, bh[nt][0], bh[nt][1]);
                    mma16816(acc[mt][nt], ah0, ah1, ah2, ah3, bl[nt][0], bl[nt][1]);
                    mma16816(acc[mt][nt], al0, al1, al2, al3, bh[nt][0], bh[nt][1]);
                }
            }
        }
        buf ^= 1;
    }

#pragma unroll
    for (int nt = 0; nt < 4; nt++) {
        const int n = n0 + wn + nt * 8 + lc * 2;
        const float2 bv = *(const float2*)(bias + n);
#pragma unroll
        for (int mt = 0; mt < 4; mt++) {
            const int m = m0 + wm + mt * 16 + lr;
            float2 o0, o1;
            if (TF32OUT) {
                o0 = make_float2(f2tf32((acc[mt][nt][0] + bv.x) * premul),
                                 f2tf32((acc[mt][nt][1] + bv.y) * premul));
                o1 = make_float2(f2tf32((acc[mt][nt][2] + bv.x) * premul),
                                 f2tf32((acc[mt][nt][3] + bv.y) * premul));
            } else {
                o0 = make_float2(acc[mt][nt][0] + bv.x, acc[mt][nt][1] + bv.y);
                o1 = make_float2(acc[mt][nt][2] + bv.x, acc[mt][nt][3] + bv.y);
            }
            *(float2*)(C + (size_t)m * N + n) = o0;
            *(float2*)(C + (size_t)(m + 8) * N + n) = o1;
        }
    }
}

__global__ __launch_bounds__(256, 2) void gemm_qkv(
    const float* __restrict__ bq, const float* __restrict__ bk,
    const float* __restrict__ bv,
    float* __restrict__ Q, float* __restrict__ K, float* __restrict__ V)
{
    const int col0 = blockIdx.x * 128;
    const int m0 = blockIdx.y * 128;
    if (col0 < D_MODEL) {
        gemm_tile_pk<true>(g_xh, g_xl, g_WqTh, g_WqTl, bq, Q, D_MODEL, KH2,
                           m0, col0, QSCALE);
    } else if (col0 < D_MODEL + KV_DIM) {
        gemm_tile_pk<true>(g_xh, g_xl, g_WkTh, g_WkTl, bk, K, KV_DIM, KH2,
                           m0, col0 - D_MODEL, 1.0f);
    } else {
        gemm_tile_pk<true>(g_xh, g_xl, g_WvTh, g_WvTl, bv, V, KV_DIM, KH2,
                           m0, col0 - D_MODEL - KV_DIM, 1.0f);
    }
}

__global__ __launch_bounds__(256, 2) void gemm_o(
    const float* __restrict__ bias, float* __restrict__ C)
{
    gemm_tile_pk<false>(g_Oh, g_Ol, g_WoTh, g_WoTl, bias, C, D_MODEL, KH2,
                        blockIdx.y * 128, blockIdx.x * 128, 1.0f);
}

// ---------------------------------------------------------------------------
// Causal GQA flash attention (tf32 mma.sync), persistent dynamic scheduling.
// Jobs (qt,h,b) pulled descending-cost from a global counter.
// ---------------------------------------------------------------------------
#define PS_ST 68
#define KS_ST 68
#define VS_ST 72
#define OFF_KS (128 * PS_ST)
#define KS_BUF (64 * KS_ST)
#define OFF_VS (OFF_KS + 2 * KS_BUF)
#define VS_BUF (64 * VS_ST)
#define ATTN_SMEM ((OFF_VS + 2 * VS_BUF) * 4)   // 106496 B

__global__ __launch_bounds__(256, 2) void attn_mma()
{
    extern __shared__ float sm[];
    const uint32_t sbase = smem_u32p(sm);
    float* Ps = sm;
    __shared__ int sjob;

    const int tid = threadIdx.x;
    const int lane = tid & 31;
    const int w = tid >> 5;
    const int lr = lane >> 2;
    const int lc = lane & 3;
    const int r0 = w * 16 + lr;
    const int sr = tid >> 2, sc0 = (tid & 3) * 16;

    for (;;) {
        __syncthreads();   // prior job done with smem + sjob
        if (tid == 0) sjob = atomicAdd(&g_jobctr, 1);
        __syncthreads();
        const int job = sjob;
        if (job >= N_JOBS) break;

        const int qt = 15 - (job >> 5);
        const int h = job & 15;
        const int b = (job >> 4) & 1;
        const int g = h >> 2;
        const int tb = b * TSEQ;
        const int nkt = 2 * qt + 2;
        const float* kbase = g_K + (size_t)tb * KV_DIM + g * HEAD_DIM;
        const float* vbase = g_V + (size_t)tb * KV_DIM + g * HEAD_DIM;

        auto stage_kv = [&](int kt) {
            const int bf = kt & 1;
            const float* kr = kbase + (size_t)(kt * 64 + sr) * KV_DIM + sc0;
            const float* vr = vbase + (size_t)(kt * 64 + sr) * KV_DIM + sc0;
            const uint32_t kd = sbase + (OFF_KS + bf * KS_BUF + sr * KS_ST + sc0) * 4;
            const uint32_t vd = sbase + (OFF_VS + bf * VS_BUF + sr * VS_ST + sc0) * 4;
#pragma unroll
            for (int i = 0; i < 4; i++) {
                cp16(kd + i * 16, kr + i * 4);
                cp16(vd + i * 16, vr + i * 4);
            }
            CP_COMMIT();
        };

        // Q tile via cp.async (pre-scaled + tf32-rounded by gemm_qkv).
        {
            const int r = tid >> 1, c0 = (tid & 1) * 32;
            const float* qr = g_Q + (size_t)(tb + qt * 128 + r) * D_MODEL
                              + h * HEAD_DIM + c0;
            const uint32_t d = sbase + (r * PS_ST + c0) * 4;
#pragma unroll
            for (int i = 0; i < 8; i++) cp16(d + i * 16, qr + i * 4);
            CP_COMMIT();
        }
        stage_kv(0);
        stage_kv(1);
        CP_WAIT2();
        __syncthreads();

        float qf[8][4];
#pragma unroll
        for (int kb8 = 0; kb8 < 8; kb8++) {
            const float* q0 = Ps + r0 * PS_ST + kb8 * 8 + lc;
            qf[kb8][0] = q0[0];
            qf[kb8][1] = q0[8 * PS_ST];
            qf[kb8][2] = q0[4];
            qf[kb8][3] = q0[8 * PS_ST + 4];
        }

        float oacc[8][4];
#pragma unroll
        for (int nt = 0; nt < 8; nt++)
#pragma unroll
            for (int j = 0; j < 4; j++) oacc[nt][j] = 0.0f;
        float m0 = -1e30f, m1 = -1e30f, l0 = 0.0f, l1 = 0.0f;

        const int qi0 = qt * 128 + r0;
        const int qi1 = qi0 + 8;

        for (int kt = 0; kt < nkt; kt++) {
            if (kt + 1 < nkt) { CP_WAIT1(); } else { CP_WAIT0(); }
            __syncthreads();
            const float* Ks = sm + OFF_KS + (kt & 1) * KS_BUF;
            const float* Vs = sm + OFF_VS + (kt & 1) * VS_BUF;

            float sa[8][4];
#pragma unroll
            for (int nt = 0; nt < 8; nt++)
#pragma unroll
                for (int j = 0; j < 4; j++) sa[nt][j] = 0.0f;
#pragma unroll
            for (int kb8 = 0; kb8 < 8; kb8++) {
                const float a0 = qf[kb8][0], a1 = qf[kb8][1];
                const float a2 = qf[kb8][2], a3 = qf[kb8][3];
                const int kb = kb8 * 8;
#pragma unroll
                for (int nt = 0; nt < 8; nt++) {
                    const float* kk = Ks + (nt * 8 + lr) * KS_ST + kb + lc;
                    mma1688(sa[nt], a0, a1, a2, a3, kk[0], kk[4]);
                }
            }

            if (kt >= 2 * qt) {
#pragma unroll
                for (int nt = 0; nt < 8; nt++) {
                    const int kj = kt * 64 + nt * 8 + 2 * lc;
                    if (kj > qi0)     sa[nt][0] = -1e30f;
                    if (kj + 1 > qi0) sa[nt][1] = -1e30f;
                    if (kj > qi1)     sa[nt][2] = -1e30f;
                    if (kj + 1 > qi1) sa[nt][3] = -1e30f;
                }
            }

            float mx0 = sa[0][0], mx1 = sa[0][2];
#pragma unroll
            for (int nt = 0; nt < 8; nt++) {
                mx0 = fmaxf(mx0, fmaxf(sa[nt][0], sa[nt][1]));
                mx1 = fmaxf(mx1, fmaxf(sa[nt][2], sa[nt][3]));
            }
            mx0 = fmaxf(mx0, __shfl_xor_sync(0xffffffffu, mx0, 1));
            mx0 = fmaxf(mx0, __shfl_xor_sync(0xffffffffu, mx0, 2));
            mx1 = fmaxf(mx1, __shfl_xor_sync(0xffffffffu, mx1, 1));
            mx1 = fmaxf(mx1, __shfl_xor_sync(0xffffffffu, mx1, 2));
            const float nm0 = fmaxf(m0, mx0), nm1 = fmaxf(m1, mx1);
            const float cf0 = exp2f(m0 - nm0), cf1 = exp2f(m1 - nm1);
            m0 = nm0; m1 = nm1;
            float rs0 = 0.0f, rs1 = 0.0f;
#pragma unroll
            for (int nt = 0; nt < 8; nt++) {
                float p0 = exp2f(sa[nt][0] - nm0);
                float p1 = exp2f(sa[nt][1] - nm0);
                float p2 = exp2f(sa[nt][2] - nm1);
                float p3 = exp2f(sa[nt][3] - nm1);
                rs0 += p0 + p1; rs1 += p2 + p3;
                sa[nt][0] = f2tf32(p0); sa[nt][1] = f2tf32(p1);
                sa[nt][2] = f2tf32(p2); sa[nt][3] = f2tf32(p3);
            }
            rs0 += __shfl_xor_sync(0xffffffffu, rs0, 1);
            rs0 += __shfl_xor_sync(0xffffffffu, rs0, 2);
            rs1 += __shfl_xor_sync(0xffffffffu, rs1, 1);
            rs1 += __shfl_xor_sync(0xffffffffu, rs1, 2);
            l0 = l0 * cf0 + rs0;
            l1 = l1 * cf1 + rs1;
#pragma unroll
            for (int nt = 0; nt < 8; nt++) {
                oacc[nt][0] *= cf0; oacc[nt][1] *= cf0;
                oacc[nt][2] *= cf1; oacc[nt][3] *= cf1;
            }

#pragma unroll
            for (int nt = 0; nt < 8; nt++) {
                *(float2*)(Ps + r0 * PS_ST + nt * 8 + 2 * lc) =
                    make_float2(sa[nt][0], sa[nt][1]);
                *(float2*)(Ps + (r0 + 8) * PS_ST + nt * 8 + 2 * lc) =
                    make_float2(sa[nt][2], sa[nt][3]);
            }
            __syncwarp();

#pragma unroll
            for (int kb = 0; kb < 64; kb += 8) {
                const float* pr = Ps + r0 * PS_ST + kb + lc;
                const float a0 = pr[0];
                const float a1 = pr[8 * PS_ST];
                const float a2 = pr[4];
                const float a3 = pr[8 * PS_ST + 4];
#pragma unroll
                for (int nt = 0; nt < 8; nt++) {
                    const float b0 = Vs[(kb + lc) * VS_ST + nt * 8 + lr];
                    const float b1 = Vs[(kb + lc + 4) * VS_ST + nt * 8 + lr];
                    mma1688(oacc[nt], a0, a1, a2, a3, b0, b1);
                }
            }
            __syncthreads();
            if (kt + 2 < nkt) stage_kv(kt + 2);
        }

        // Normalize; write packed bf16x2 hi/lo (feeds gemm_o).
        const float inv0 = 1.0f / l0, inv1 = 1.0f / l1;
        const size_t row0 = (size_t)(tb + qt * 128 + r0);
        const int colp = h * 32 + lc;
#pragma unroll
        for (int nt = 0; nt < 8; nt++) {
            float v0 = oacc[nt][0] * inv0, v1 = oacc[nt][1] * inv0;
            float v2 = oacc[nt][2] * inv1, v3 = oacc[nt][3] * inv1;
            __nv_bfloat16 h0 = __float2bfloat16_rn(v0);
            __nv_bfloat16 h1 = __float2bfloat16_rn(v1);
            __nv_bfloat16 h2 = __float2bfloat16_rn(v2);
            __nv_bfloat16 h3 = __float2bfloat16_rn(v3);
            const size_t o0 = row0 * KH2 + colp + nt * 4;
            const size_t o1 = (row0 + 8) * KH2 + colp + nt * 4;
            g_Oh[o0] = packbf(h0, h1);
            g_Ol[o0] = packbf(__float2bfloat16_rn(v0 - __bfloat162float(h0)),
                              __float2bfloat16_rn(v1 - __bfloat162float(h1)));
            g_Oh[o1] = packbf(h2, h3);
            g_Ol[o1] = packbf(__float2bfloat16_rn(v2 - __bfloat162float(h2)),
                              __float2bfloat16_rn(v3 - __bfloat162float(h3)));
        }
    }
}

// ---------------------------------------------------------------------------
extern "C" void kernel_launch(void* const* d_in, const int* in_sizes, int n_in,
                              void* d_out, int out_size)
{
    const float* x  = (const float*)d_in[0];
    const float* Wq = (const float*)d_in[1];
    const float* bq = (const float*)d_in[2];
    const float* Wk = (const float*)d_in[3];
    const float* bk = (const float*)d_in[4];
    const float* Wv = (const float*)d_in[5];
    const float* bv = (const float*)d_in[6];
    const float* Wo = (const float*)d_in[7];
    const float* bo = (const float*)d_in[8];
    float* out = (float*)d_out;

    float *Qp, *Kp, *Vp;
    uint32_t *xh, *xl;
    cudaGetSymbolAddress((void**)&Qp, g_Q);
    cudaGetSymbolAddress((void**)&Kp, g_K);
    cudaGetSymbolAddress((void**)&Vp, g_V);
    cudaGetSymbolAddress((void**)&xh, g_xh);
    cudaGetSymbolAddress((void**)&xl, g_xl);

    cudaFuncSetAttribute(gemm_qkv, cudaFuncAttributeMaxDynamicSharedMemorySize, GEMM_SMEM);
    cudaFuncSetAttribute(gemm_o,   cudaFuncAttributeMaxDynamicSharedMemorySize, GEMM_SMEM);
    cudaFuncSetAttribute(attn_mma, cudaFuncAttributeMaxDynamicSharedMemorySize, ATTN_SMEM);

    // One-shot conversions + job counter reset.
    conv_pack<<<(BT * D_MODEL / 4 + 255) / 256, 256>>>(x, xh, xl, BT * D_MODEL / 4);
    conv_wT_all<<<dim3(D_MODEL / 32, D_MODEL / 32, 4), dim3(32, 8)>>>(Wq, Wk, Wv, Wo);
    reset_ctr<<<1, 32>>>();

    // Fused QKV projection (Q pre-scaled + tf32-rounded; K/V tf32-rounded).
    gemm_qkv<<<dim3((D_MODEL + 2 * KV_DIM) / 128, BT / 128), 256, GEMM_SMEM>>>(
        bq, bk, bv, Qp, Kp, Vp);

    // Causal GQA attention (persistent CTAs, dynamic job scheduling).
    attn_mma<<<304, 256, ATTN_SMEM>>>();

    // Output projection.
    gemm_o<<<dim3(D_MODEL / 128, BT / 128), 256, GEMM_SMEM>>>(bo, out);
}

// round 12
// speedup vs baseline: 1.3495x; 1.0258x over previous
#include <cuda_runtime.h>
#include <cuda_bf16.h>
#include <cstdint>

#define D_MODEL 1024
#define KV_DIM 256
#define N_HEADS 16
#define HEAD_DIM 64
#define TSEQ 2048
#define BATCH 2
#define BT (BATCH * TSEQ)
#define KH2 (D_MODEL / 2)
#define QSCALE (0.125f * 1.4426950408889634f)   // 1/sqrt(64) * log2(e)
#define N_JOBS (16 * N_HEADS * BATCH)           // 512 attention tile-jobs
#define PLANE (TSEQ * HEAD_DIM)                 // 131072 floats per (b,g)

// Scratch (device globals; no allocation anywhere).
__device__ float g_Q[(size_t)BT * D_MODEL];
// K interleaved: plane(b,g) -> [t][pair p = (d>>3)*4 + (d&3)] float2, half=(d>>2)&1
__device__ float g_Kp[(size_t)BT * KV_DIM];
// V interleaved: plane(b,g) -> [q = (t>>3)*4 + (t&3)][d] float2, half=(t>>2)&1
__device__ float g_Vp[(size_t)BT * KV_DIM];
__device__ int g_jobctr;
// packed bf16x2 hi/lo operands
__device__ uint32_t g_xh[(size_t)BT * KH2];
__device__ uint32_t g_xl[(size_t)BT * KH2];
__device__ uint32_t g_Oh[(size_t)BT * KH2];
__device__ uint32_t g_Ol[(size_t)BT * KH2];
__device__ uint32_t g_WqTh[(size_t)D_MODEL * KH2];
__device__ uint32_t g_WqTl[(size_t)D_MODEL * KH2];
__device__ uint32_t g_WkTh[(size_t)KV_DIM * KH2];
__device__ uint32_t g_WkTl[(size_t)KV_DIM * KH2];
__device__ uint32_t g_WvTh[(size_t)KV_DIM * KH2];
__device__ uint32_t g_WvTl[(size_t)KV_DIM * KH2];
__device__ uint32_t g_WoTh[(size_t)D_MODEL * KH2];
__device__ uint32_t g_WoTl[(size_t)D_MODEL * KH2];

// ---------------------------------------------------------------------------
// Helpers
// ---------------------------------------------------------------------------
__device__ __forceinline__ float f2tf32(float v) {
    uint32_t u; asm("cvt.rna.tf32.f32 %0, %1;" : "=r"(u) : "f"(v));
    return __uint_as_float(u);
}

__device__ __forceinline__ void mma1688(float* d, float a0, float a1, float a2,
                                        float a3, float b0, float b1) {
    asm volatile(
        "mma.sync.aligned.m16n8k8.row.col.f32.tf32.tf32.f32 "
        "{%0,%1,%2,%3}, {%4,%5,%6,%7}, {%8,%9}, {%0,%1,%2,%3};"
        : "+f"(d[0]), "+f"(d[1]), "+f"(d[2]), "+f"(d[3])
        : "r"(__float_as_uint(a0)), "r"(__float_as_uint(a1)),
          "r"(__float_as_uint(a2)), "r"(__float_as_uint(a3)),
          "r"(__float_as_uint(b0)), "r"(__float_as_uint(b1)));
}

__device__ __forceinline__ void mma16816(float* d, uint32_t a0, uint32_t a1,
                                         uint32_t a2, uint32_t a3,
                                         uint32_t b0, uint32_t b1) {
    asm volatile(
        "mma.sync.aligned.m16n8k16.row.col.f32.bf16.bf16.f32 "
        "{%0,%1,%2,%3}, {%4,%5,%6,%7}, {%8,%9}, {%0,%1,%2,%3};"
        : "+f"(d[0]), "+f"(d[1]), "+f"(d[2]), "+f"(d[3])
        : "r"(a0), "r"(a1), "r"(a2), "r"(a3), "r"(b0), "r"(b1));
}

__device__ __forceinline__ void ldsm4(uint32_t& r0, uint32_t& r1,
                                      uint32_t& r2, uint32_t& r3, uint32_t a) {
    asm volatile("ldmatrix.sync.aligned.m8n8.x4.shared.b16 {%0,%1,%2,%3}, [%4];"
                 : "=r"(r0), "=r"(r1), "=r"(r2), "=r"(r3) : "r"(a));
}

__device__ __forceinline__ uint32_t packbf(__nv_bfloat16 a, __nv_bfloat16 b) {
    __nv_bfloat162 t(a, b);
    return *reinterpret_cast<uint32_t*>(&t);
}

__device__ __forceinline__ uint32_t smem_u32p(const void* p) {
    uint32_t r;
    asm("{ .reg .u64 t; cvta.to.shared.u64 t, %1; cvt.u32.u64 %0, t; }"
        : "=r"(r) : "l"(p));
    return r;
}

__device__ __forceinline__ void cp16(uint32_t dst, const void* src) {
    asm volatile("cp.async.cg.shared.global [%0], [%1], 16;"
                 :: "r"(dst), "l"(src));
}
#define CP_COMMIT() asm volatile("cp.async.commit_group;" ::: "memory")
#define CP_WAIT0()  asm volatile("cp.async.wait_group 0;" ::: "memory")
#define CP_WAIT1()  asm volatile("cp.async.wait_group 1;" ::: "memory")
#define CP_WAIT2()  asm volatile("cp.async.wait_group 2;" ::: "memory")

// Interleaved address helpers (float index within g_Kp / g_Vp).
__device__ __forceinline__ size_t kaddr(int m, int n) {
    const int t = m & (TSEQ - 1), d = n & 63;
    const size_t plane = (size_t)(((m >> 11) << 2) + (n >> 6)) * PLANE;
    return plane + (size_t)t * 64 + (((d >> 3) * 4 + (d & 3)) << 1) + ((d >> 2) & 1);
}
__device__ __forceinline__ size_t vaddr(int m, int n) {
    const int t = m & (TSEQ - 1), d = n & 63;
    const int q = ((t >> 3) << 2) + (t & 3);
    const size_t plane = (size_t)(((m >> 11) << 2) + (n >> 6)) * PLANE;
    return plane + (size_t)q * 128 + (d << 1) + ((t >> 2) & 1);
}

// ---------------------------------------------------------------------------
// One-shot converters
// ---------------------------------------------------------------------------
__global__ __launch_bounds__(256) void conv_pack(
    const float* __restrict__ A, uint32_t* __restrict__ H,
    uint32_t* __restrict__ L, int n4)
{
    int i = blockIdx.x * blockDim.x + threadIdx.x;
    if (i == 0) g_jobctr = 0;
    if (i >= n4) return;
    float4 v = ((const float4*)A)[i];
    __nv_bfloat16 hx = __float2bfloat16_rn(v.x);
    __nv_bfloat16 hy = __float2bfloat16_rn(v.y);
    __nv_bfloat16 hz = __float2bfloat16_rn(v.z);
    __nv_bfloat16 hw = __float2bfloat16_rn(v.w);
    ((uint2*)H)[i] = make_uint2(packbf(hx, hy), packbf(hz, hw));
    ((uint2*)L)[i] = make_uint2(
        packbf(__float2bfloat16_rn(v.x - __bfloat162float(hx)),
               __float2bfloat16_rn(v.y - __bfloat162float(hy))),
        packbf(__float2bfloat16_rn(v.z - __bfloat162float(hz)),
               __float2bfloat16_rn(v.w - __bfloat162float(hw))));
}

__global__ __launch_bounds__(256) void conv_wT_all(
    const float* __restrict__ Wq, const float* __restrict__ Wk,
    const float* __restrict__ Wv, const float* __restrict__ Wo)
{
    const float* W; uint32_t* H; uint32_t* L; int N;
    switch (blockIdx.z) {
        case 0: W = Wq; H = g_WqTh; L = g_WqTl; N = D_MODEL; break;
        case 1: W = Wk; H = g_WkTh; L = g_WkTl; N = KV_DIM;  break;
        case 2: W = Wv; H = g_WvTh; L = g_WvTl; N = KV_DIM;  break;
        default:W = Wo; H = g_WoTh; L = g_WoTl; N = D_MODEL; break;
    }
    const int n0 = blockIdx.x * 32, k0 = blockIdx.y * 32;
    if (n0 >= N) return;
    __shared__ float t[32][33];
    const int tx = threadIdx.x, ty = threadIdx.y;
#pragma unroll
    for (int i = 0; i < 4; i++)
        t[ty + i * 8][tx] = W[(size_t)(k0 + ty + i * 8) * N + n0 + tx];
    __syncthreads();
#pragma unroll
    for (int i = 0; i < 2; i++) {
        const int kp = ty + i * 8;
        float a = t[kp * 2][tx], b = t[kp * 2 + 1][tx];
        __nv_bfloat16 ha = __float2bfloat16_rn(a);
        __nv_bfloat16 hb = __float2bfloat16_rn(b);
        const size_t o = (size_t)(n0 + tx) * KH2 + k0 / 2 + kp;
        H[o] = packbf(ha, hb);
        L[o] = packbf(__float2bfloat16_rn(a - __bfloat162float(ha)),
                      __float2bfloat16_rn(b - __bfloat162float(hb)));
    }
}

// ---------------------------------------------------------------------------
// 2-term bf16-split GEMM, cp.async double-buffered, ldmatrix fragment loads.
// MODE: 0 = plain fp32 store; 1 = tf32(premul) row-major (Q);
//       2 = tf32 K-interleaved scatter; 3 = tf32 V-interleaved scatter.
// ---------------------------------------------------------------------------
#define GROW 20
#define G_AH 0
#define G_AL (128 * GROW)
#define G_BH (2 * 128 * GROW)
#define G_BL (3 * 128 * GROW)
#define G_U32 (4 * 128 * GROW)
#define GEMM_SMEM (2 * G_U32 * 4)

__device__ __forceinline__ void gemm_stage(
    uint32_t sbase, const uint32_t* __restrict__ AH,
    const uint32_t* __restrict__ AL, const uint32_t* __restrict__ BH,
    const uint32_t* __restrict__ BL, int KH, int m0, int n0, int kc2)
{
    const int tid = threadIdx.x;
#pragma unroll
    for (int j = 0; j < 2; j++) {
        const int idx = tid + j * 256;
        const int r = idx >> 2, sg = (idx & 3) * 4;
        const size_t ao = (size_t)(m0 + r) * KH + kc2 + sg;
        const size_t bo = (size_t)(n0 + r) * KH + kc2 + sg;
        const uint32_t d = sbase + (r * GROW + sg) * 4;
        cp16(d + G_AH * 4, AH + ao);
        cp16(d + G_AL * 4, AL + ao);
        cp16(d + G_BH * 4, BH + bo);
        cp16(d + G_BL * 4, BL + bo);
    }
    CP_COMMIT();
}

template <int MODE>
__device__ __forceinline__ void gemm_tile_pk(
    const uint32_t* __restrict__ AH, const uint32_t* __restrict__ AL,
    const uint32_t* __restrict__ BH, const uint32_t* __restrict__ BL,
    const float* __restrict__ bias, float* __restrict__ C,
    int N, int KH, int m0, int n0, float premul)
{
    extern __shared__ uint32_t su[];
    const uint32_t sbase = smem_u32p(su);

    const int tid = threadIdx.x;
    const int lane = tid & 31;
    const int wid = tid >> 5;
    const int wm = (wid >> 2) * 64;
    const int wn = (wid & 3) * 32;
    const int lr = lane >> 2;
    const int lc = lane & 3;
    const int lt = lane >> 3;
    const int lrr = lane & 7;

    const uint32_t aBase = sbase +
        (((wm + (lt & 1) * 8 + lrr) * GROW + (lt >> 1) * 4) << 2);
    const uint32_t bBase = sbase +
        ((G_BH + (wn + (lt >> 1) * 8 + lrr) * GROW + (lt & 1) * 4) << 2);

    float acc[4][4][4];
#pragma unroll
    for (int i = 0; i < 4; i++)
#pragma unroll
        for (int j = 0; j < 4; j++)
#pragma unroll
            for (int k = 0; k < 4; k++) acc[i][j][k] = 0.0f;

    const int NC = KH / 16;
    int buf = 0;

    gemm_stage(sbase, AH, AL, BH, BL, KH, m0, n0, 0);

    for (int c = 0; c < NC; c++) {
        CP_WAIT0();
        __syncthreads();
        if (c + 1 < NC)
            gemm_stage(sbase + (buf ^ 1) * G_U32 * 4,
                       AH, AL, BH, BL, KH, m0, n0, (c + 1) * 16);

        const uint32_t bufo = (uint32_t)buf * G_U32 * 4;
#pragma unroll
        for (int ss = 0; ss < 2; ss++) {
            uint32_t bh[4][2], bl[4][2];
#pragma unroll
            for (int p = 0; p < 2; p++) {
                const uint32_t off = bufo + ((p * 16 * GROW + ss * 8) << 2);
                ldsm4(bh[2 * p][0], bh[2 * p][1], bh[2 * p + 1][0],
                      bh[2 * p + 1][1], bBase + off);
                ldsm4(bl[2 * p][0], bl[2 * p][1], bl[2 * p + 1][0],
                      bl[2 * p + 1][1], bBase + off + ((128 * GROW) << 2));
            }
#pragma unroll
            for (int mt = 0; mt < 4; mt++) {
                const uint32_t off = bufo + ((mt * 16 * GROW + ss * 8) << 2);
                uint32_t ah0, ah1, ah2, ah3, al0, al1, al2, al3;
                ldsm4(ah0, ah1, ah2, ah3, aBase + off);
                ldsm4(al0, al1, al2, al3, aBase + off + ((G_AL) << 2));
#pragma unroll
                for (int nt = 0; nt < 4; nt++) {
                    mma16816(acc[mt][nt], ah0, ah1, ah2, ah3, bh[nt][0], bh[nt][1]);
                    mma16816(acc[mt][nt], ah0, ah1, ah2, ah3, bl[nt][0], bl[nt][1]);
                    mma16816(acc[mt][nt], al0, al1, al2, al3, bh[nt][0], bh[nt][1]);
                }
            }
        }
        buf ^= 1;
    }

#pragma unroll
    for (int nt = 0; nt < 4; nt++) {
        const int n = n0 + wn + nt * 8 + lc * 2;
        const float2 bv = *(const float2*)(bias + n);
#pragma unroll
        for (int mt = 0; mt < 4; mt++) {
            const int m = m0 + wm + mt * 16 + lr;
            if (MODE == 0) {
                *(float2*)(C + (size_t)m * N + n) =
                    make_float2(acc[mt][nt][0] + bv.x, acc[mt][nt][1] + bv.y);
                *(float2*)(C + (size_t)(m + 8) * N + n) =
                    make_float2(acc[mt][nt][2] + bv.x, acc[mt][nt][3] + bv.y);
            } else if (MODE == 1) {
                *(float2*)(C + (size_t)m * N + n) =
                    make_float2(f2tf32((acc[mt][nt][0] + bv.x) * premul),
                                f2tf32((acc[mt][nt][1] + bv.y) * premul));
                *(float2*)(C + (size_t)(m + 8) * N + n) =
                    make_float2(f2tf32((acc[mt][nt][2] + bv.x) * premul),
                                f2tf32((acc[mt][nt][3] + bv.y) * premul));
            } else if (MODE == 2) {
                C[kaddr(m, n)]         = f2tf32(acc[mt][nt][0] + bv.x);
                C[kaddr(m, n + 1)]     = f2tf32(acc[mt][nt][1] + bv.y);
                C[kaddr(m + 8, n)]     = f2tf32(acc[mt][nt][2] + bv.x);
                C[kaddr(m + 8, n + 1)] = f2tf32(acc[mt][nt][3] + bv.y);
            } else {
                C[vaddr(m, n)]         = f2tf32(acc[mt][nt][0] + bv.x);
                C[vaddr(m, n + 1)]     = f2tf32(acc[mt][nt][1] + bv.y);
                C[vaddr(m + 8, n)]     = f2tf32(acc[mt][nt][2] + bv.x);
                C[vaddr(m + 8, n + 1)] = f2tf32(acc[mt][nt][3] + bv.y);
            }
        }
    }
}

__global__ __launch_bounds__(256, 2) void gemm_qkv(
    const float* __restrict__ bq, const float* __restrict__ bk,
    const float* __restrict__ bv,
    float* __restrict__ Q, float* __restrict__ K, float* __restrict__ V)
{
    const int col0 = blockIdx.x * 128;
    const int m0 = blockIdx.y * 128;
    if (col0 < D_MODEL) {
        gemm_tile_pk<1>(g_xh, g_xl, g_WqTh, g_WqTl, bq, Q, D_MODEL, KH2,
                        m0, col0, QSCALE);
    } else if (col0 < D_MODEL + KV_DIM) {
        gemm_tile_pk<2>(g_xh, g_xl, g_WkTh, g_WkTl, bk, K, KV_DIM, KH2,
                        m0, col0 - D_MODEL, 1.0f);
    } else {
        gemm_tile_pk<3>(g_xh, g_xl, g_WvTh, g_WvTl, bv, V, KV_DIM, KH2,
                        m0, col0 - D_MODEL - KV_DIM, 1.0f);
    }
}

__global__ __launch_bounds__(256, 2) void gemm_o(
    const float* __restrict__ bias, float* __restrict__ C)
{
    gemm_tile_pk<0>(g_Oh, g_Ol, g_WoTh, g_WoTl, bias, C, D_MODEL, KH2,
                    blockIdx.y * 128, blockIdx.x * 128, 1.0f);
}

// ---------------------------------------------------------------------------
// Causal GQA flash attention (tf32 mma.sync), persistent dynamic scheduling.
// K/V arrive fragment-pair-interleaved from gemm_qkv: all B-fragment loads
// are single LDS.64 (halves mainloop LDS count).
// ---------------------------------------------------------------------------
#define PS_ST 68
#define KS_ST 72      // 64 payload + 8 pad (≡8 mod 32: conflict-free float2)
#define VS_ST 136     // 128 payload + 8 pad (≡8 mod 32)
#define OFF_KS (128 * PS_ST)            // 8704
#define KS_BUF (64 * KS_ST)             // 4608
#define OFF_VS (OFF_KS + 2 * KS_BUF)    // 17920
#define VS_BUF (32 * VS_ST)             // 4352
#define ATTN_SMEM ((OFF_VS + 2 * VS_BUF) * 4)   // 106496 B

__global__ __launch_bounds__(256, 2) void attn_mma()
{
    extern __shared__ float sm[];
    const uint32_t sbase = smem_u32p(sm);
    float* Ps = sm;
    __shared__ int sjob;

    const int tid = threadIdx.x;
    const int lane = tid & 31;
    const int w = tid >> 5;
    const int lr = lane >> 2;
    const int lc = lane & 3;
    const int r0 = w * 16 + lr;

    for (;;) {
        __syncthreads();
        if (tid == 0) sjob = atomicAdd(&g_jobctr, 1);
        __syncthreads();
        const int job = sjob;
        if (job >= N_JOBS) break;

        const int qt = 15 - (job >> 5);
        const int h = job & 15;
        const int b = (job >> 4) & 1;
        const int g = h >> 2;
        const int tb = b * TSEQ;
        const int nkt = 2 * qt + 2;
        const float* kbase = g_Kp + (size_t)(b * 4 + g) * PLANE;
        const float* vbase = g_Vp + (size_t)(b * 4 + g) * PLANE;

        auto stage_kv = [&](int kt) {
            const int bf = kt & 1;
            // K: 64 keys x 64 floats (interleaved pairs), contiguous per key.
            const int krow = tid >> 2, kseg = (tid & 3) * 16;
            const float* kr = kbase + (size_t)(kt * 64 + krow) * 64 + kseg;
            const uint32_t kd = sbase + (OFF_KS + bf * KS_BUF + krow * KS_ST + kseg) * 4;
            // V: 32 q-rows x 128 floats, contiguous per q-row.
            const int vrow = tid >> 3, vseg = (tid & 7) * 16;
            const float* vr = vbase + (size_t)(kt * 32 + vrow) * 128 + vseg;
            const uint32_t vd = sbase + (OFF_VS + bf * VS_BUF + vrow * VS_ST + vseg) * 4;
#pragma unroll
            for (int i = 0; i < 4; i++) {
                cp16(kd + i * 16, kr + i * 4);
                cp16(vd + i * 16, vr + i * 4);
            }
            CP_COMMIT();
        };

        // Q tile via cp.async (pre-scaled + tf32-rounded by gemm_qkv).
        {
            const int r = tid >> 1, c0 = (tid & 1) * 32;
            const float* qr = g_Q + (size_t)(tb + qt * 128 + r) * D_MODEL
                              + h * HEAD_DIM + c0;
            const uint32_t d = sbase + (r * PS_ST + c0) * 4;
#pragma unroll
            for (int i = 0; i < 8; i++) cp16(d + i * 16, qr + i * 4);
            CP_COMMIT();
        }
        stage_kv(0);
        stage_kv(1);
        CP_WAIT2();
        __syncthreads();

        float qf[8][4];
#pragma unroll
        for (int kb8 = 0; kb8 < 8; kb8++) {
            const float* q0 = Ps + r0 * PS_ST + kb8 * 8 + lc;
            qf[kb8][0] = q0[0];
            qf[kb8][1] = q0[8 * PS_ST];
            qf[kb8][2] = q0[4];
            qf[kb8][3] = q0[8 * PS_ST + 4];
        }

        float oacc[8][4];
#pragma unroll
        for (int nt = 0; nt < 8; nt++)
#pragma unroll
            for (int j = 0; j < 4; j++) oacc[nt][j] = 0.0f;
        float m0 = -1e30f, m1 = -1e30f, l0 = 0.0f, l1 = 0.0f;

        const int qi0 = qt * 128 + r0;
        const int qi1 = qi0 + 8;

        for (int kt = 0; kt < nkt; kt++) {
            if (kt + 1 < nkt) { CP_WAIT1(); } else { CP_WAIT0(); }
            __syncthreads();
            const float* Ks = sm + OFF_KS + (kt & 1) * KS_BUF;
            const float* Vs = sm + OFF_VS + (kt & 1) * VS_BUF;

            // S = Q @ K^T  — B fragment is one LDS.64.
            float sa[8][4];
#pragma unroll
            for (int nt = 0; nt < 8; nt++)
#pragma unroll
                for (int j = 0; j < 4; j++) sa[nt][j] = 0.0f;
#pragma unroll
            for (int kb8 = 0; kb8 < 8; kb8++) {
                const float a0 = qf[kb8][0], a1 = qf[kb8][1];
                const float a2 = qf[kb8][2], a3 = qf[kb8][3];
#pragma unroll
                for (int nt = 0; nt < 8; nt++) {
                    const float2 kk = *(const float2*)(Ks +
                        (nt * 8 + lr) * KS_ST + (kb8 * 4 + lc) * 2);
                    mma1688(sa[nt], a0, a1, a2, a3, kk.x, kk.y);
                }
            }

            if (kt >= 2 * qt) {
#pragma unroll
                for (int nt = 0; nt < 8; nt++) {
                    const int kj = kt * 64 + nt * 8 + 2 * lc;
                    if (kj > qi0)     sa[nt][0] = -1e30f;
                    if (kj + 1 > qi0) sa[nt][1] = -1e30f;
                    if (kj > qi1)     sa[nt][2] = -1e30f;
                    if (kj + 1 > qi1) sa[nt][3] = -1e30f;
                }
            }

            float mx0 = sa[0][0], mx1 = sa[0][2];
#pragma unroll
            for (int nt = 0; nt < 8; nt++) {
                mx0 = fmaxf(mx0, fmaxf(sa[nt][0], sa[nt][1]));
                mx1 = fmaxf(mx1, fmaxf(sa[nt][2], sa[nt][3]));
            }
            mx0 = fmaxf(mx0, __shfl_xor_sync(0xffffffffu, mx0, 1));
            mx0 = fmaxf(mx0, __shfl_xor_sync(0xffffffffu, mx0, 2));
            mx1 = fmaxf(mx1, __shfl_xor_sync(0xffffffffu, mx1, 1));
            mx1 = fmaxf(mx1, __shfl_xor_sync(0xffffffffu, mx1, 2));
            const float nm0 = fmaxf(m0, mx0), nm1 = fmaxf(m1, mx1);
            const float cf0 = exp2f(m0 - nm0), cf1 = exp2f(m1 - nm1);
            m0 = nm0; m1 = nm1;
            float rs0 = 0.0f, rs1 = 0.0f;
#pragma unroll
            for (int nt = 0; nt < 8; nt++) {
                float p0 = exp2f(sa[nt][0] - nm0);
                float p1 = exp2f(sa[nt][1] - nm0);
                float p2 = exp2f(sa[nt][2] - nm1);
                float p3 = exp2f(sa[nt][3] - nm1);
                rs0 += p0 + p1; rs1 += p2 + p3;
                sa[nt][0] = f2tf32(p0); sa[nt][1] = f2tf32(p1);
                sa[nt][2] = f2tf32(p2); sa[nt][3] = f2tf32(p3);
            }
            rs0 += __shfl_xor_sync(0xffffffffu, rs0, 1);
            rs0 += __shfl_xor_sync(0xffffffffu, rs0, 2);
            rs1 += __shfl_xor_sync(0xffffffffu, rs1, 1);
            rs1 += __shfl_xor_sync(0xffffffffu, rs1, 2);
            l0 = l0 * cf0 + rs0;
            l1 = l1 * cf1 + rs1;
#pragma unroll
            for (int nt = 0; nt < 8; nt++) {
                oacc[nt][0] *= cf0; oacc[nt][1] *= cf0;
                oacc[nt][2] *= cf1; oacc[nt][3] *= cf1;
            }

#pragma unroll
            for (int nt = 0; nt < 8; nt++) {
                *(float2*)(Ps + r0 * PS_ST + nt * 8 + 2 * lc) =
                    make_float2(sa[nt][0], sa[nt][1]);
                *(float2*)(Ps + (r0 + 8) * PS_ST + nt * 8 + 2 * lc) =
                    make_float2(sa[nt][2], sa[nt][3]);
            }
            __syncwarp();

            // O += P @ V — B fragment is one LDS.64.
#pragma unroll
            for (int kb8 = 0; kb8 < 8; kb8++) {
                const float* pr = Ps + r0 * PS_ST + kb8 * 8 + lc;
                const float a0 = pr[0];
                const float a1 = pr[8 * PS_ST];
                const float a2 = pr[4];
                const float a3 = pr[8 * PS_ST + 4];
#pragma unroll
                for (int nt = 0; nt < 8; nt++) {
                    const float2 vv = *(const float2*)(Vs +
                        (kb8 * 4 + lc) * VS_ST + (nt * 8 + lr) * 2);
                    mma1688(oacc[nt], a0, a1, a2, a3, vv.x, vv.y);
                }
            }
            __syncthreads();
            if (kt + 2 < nkt) stage_kv(kt + 2);
        }

        // Normalize; write packed bf16x2 hi/lo (feeds gemm_o).
        const float inv0 = 1.0f / l0, inv1 = 1.0f / l1;
        const size_t row0 = (size_t)(tb + qt * 128 + r0);
        const int colp = h * 32 + lc;
#pragma unroll
        for (int nt = 0; nt < 8; nt++) {
            float v0 = oacc[nt][0] * inv0, v1 = oacc[nt][1] * inv0;
            float v2 = oacc[nt][2] * inv1, v3 = oacc[nt][3] * inv1;
            __nv_bfloat16 h0 = __float2bfloat16_rn(v0);
            __nv_bfloat16 h1 = __float2bfloat16_rn(v1);
            __nv_bfloat16 h2 = __float2bfloat16_rn(v2);
            __nv_bfloat16 h3 = __float2bfloat16_rn(v3);
            const size_t o0 = row0 * KH2 + colp + nt * 4;
            const size_t o1 = (row0 + 8) * KH2 + colp + nt * 4;
            g_Oh[o0] = packbf(h0, h1);
            g_Ol[o0] = packbf(__float2bfloat16_rn(v0 - __bfloat162float(h0)),
                              __float2bfloat16_rn(v1 - __bfloat162float(h1)));
            g_Oh[o1] = packbf(h2, h3);
            g_Ol[o1] = packbf(__float2bfloat16_rn(v2 - __bfloat162float(h2)),
                              __float2bfloat16_rn(v3 - __bfloat162float(h3)));
        }
    }
}

// ---------------------------------------------------------------------------
extern "C" void kernel_launch(void* const* d_in, const int* in_sizes, int n_in,
                              void* d_out, int out_size)
{
    const float* x  = (const float*)d_in[0];
    const float* Wq = (const float*)d_in[1];
    const float* bq = (const float*)d_in[2];
    const float* Wk = (const float*)d_in[3];
    const float* bk = (const float*)d_in[4];
    const float* Wv = (const float*)d_in[5];
    const float* bv = (const float*)d_in[6];
    const float* Wo = (const float*)d_in[7];
    const float* bo = (const float*)d_in[8];
    float* out = (float*)d_out;

    float *Qp, *Kp, *Vp;
    uint32_t *xh, *xl;
    cudaGetSymbolAddress((void**)&Qp, g_Q);
    cudaGetSymbolAddress((void**)&Kp, g_Kp);
    cudaGetSymbolAddress((void**)&Vp, g_Vp);
    cudaGetSymbolAddress((void**)&xh, g_xh);
    cudaGetSymbolAddress((void**)&xl, g_xl);

    cudaFuncSetAttribute(gemm_qkv, cudaFuncAttributeMaxDynamicSharedMemorySize, GEMM_SMEM);
    cudaFuncSetAttribute(gemm_o,   cudaFuncAttributeMaxDynamicSharedMemorySize, GEMM_SMEM);
    cudaFuncSetAttribute(attn_mma, cudaFuncAttributeMaxDynamicSharedMemorySize, ATTN_SMEM);

    // One-shot conversions (+ job counter reset inside conv_pack).
    conv_pack<<<(BT * D_MODEL / 4 + 255) / 256, 256>>>(x, xh, xl, BT * D_MODEL / 4);
    conv_wT_all<<<dim3(D_MODEL / 32, D_MODEL / 32, 4), dim3(32, 8)>>>(Wq, Wk, Wv, Wo);

    // Fused QKV projection (Q tf32+scaled; K/V tf32, fragment-interleaved).
    gemm_qkv<<<dim3((D_MODEL + 2 * KV_DIM) / 128, BT / 128), 256, GEMM_SMEM>>>(
        bq, bk, bv, Qp, Kp, Vp);

    // Causal GQA attention (persistent CTAs, dynamic job scheduling).
    attn_mma<<<304, 256, ATTN_SMEM>>>();

    // Output projection.
    gemm_o<<<dim3(D_MODEL / 128, BT / 128), 256, GEMM_SMEM>>>(bo, out);
}

// round 14
// speedup vs baseline: 1.3573x; 1.0057x over previous
#include <cuda_runtime.h>
#include <cuda_bf16.h>
#include <cstdint>

#define D_MODEL 1024
#define KV_DIM 256
#define N_HEADS 16
#define HEAD_DIM 64
#define TSEQ 2048
#define BATCH 2
#define BT (BATCH * TSEQ)
#define KH2 (D_MODEL / 2)
#define QSCALE (0.125f * 1.4426950408889634f)   // 1/sqrt(64) * log2(e)
#define N_JOBS (16 * N_HEADS * BATCH)           // 512 attention tile-jobs
#define PLANE (TSEQ * HEAD_DIM)                 // 131072 floats per (b,g)

// Scratch (device globals; no allocation anywhere).
__device__ float g_Q[(size_t)BT * D_MODEL];
// K quad-interleaved: plane(b,g) -> [t][pos(d)], pos = (d>>4)*16+(d&3)*4+((d>>2)&3)
__device__ float g_Kp[(size_t)BT * KV_DIM];
// V t-quad-interleaved (tf32): plane(b,g) ->
//   [blk=t>>4][d][(t&3)*4 + ((t>>2)&3)]   (blk stride 1024, d stride 16)
__device__ float g_Vp[(size_t)BT * KV_DIM];
__device__ int g_jobctr;
// packed bf16x2 hi/lo operands
__device__ uint32_t g_xh[(size_t)BT * KH2];
__device__ uint32_t g_xl[(size_t)BT * KH2];
__device__ uint32_t g_Oh[(size_t)BT * KH2];
__device__ uint32_t g_Ol[(size_t)BT * KH2];
__device__ uint32_t g_WqTh[(size_t)D_MODEL * KH2];
__device__ uint32_t g_WqTl[(size_t)D_MODEL * KH2];
__device__ uint32_t g_WkTh[(size_t)KV_DIM * KH2];
__device__ uint32_t g_WkTl[(size_t)KV_DIM * KH2];
__device__ uint32_t g_WvTh[(size_t)KV_DIM * KH2];
__device__ uint32_t g_WvTl[(size_t)KV_DIM * KH2];
__device__ uint32_t g_WoTh[(size_t)D_MODEL * KH2];
__device__ uint32_t g_WoTl[(size_t)D_MODEL * KH2];

// ---------------------------------------------------------------------------
// Helpers
// ---------------------------------------------------------------------------
__device__ __forceinline__ float f2tf32(float v) {
    uint32_t u; asm("cvt.rna.tf32.f32 %0, %1;" : "=r"(u) : "f"(v));
    return __uint_as_float(u);
}

__device__ __forceinline__ void mma1688(float* d, float a0, float a1, float a2,
                                        float a3, float b0, float b1) {
    asm volatile(
        "mma.sync.aligned.m16n8k8.row.col.f32.tf32.tf32.f32 "
        "{%0,%1,%2,%3}, {%4,%5,%6,%7}, {%8,%9}, {%0,%1,%2,%3};"
        : "+f"(d[0]), "+f"(d[1]), "+f"(d[2]), "+f"(d[3])
        : "r"(__float_as_uint(a0)), "r"(__float_as_uint(a1)),
          "r"(__float_as_uint(a2)), "r"(__float_as_uint(a3)),
          "r"(__float_as_uint(b0)), "r"(__float_as_uint(b1)));
}

__device__ __forceinline__ void mma16816(float* d, uint32_t a0, uint32_t a1,
                                         uint32_t a2, uint32_t a3,
                                         uint32_t b0, uint32_t b1) {
    asm volatile(
        "mma.sync.aligned.m16n8k16.row.col.f32.bf16.bf16.f32 "
        "{%0,%1,%2,%3}, {%4,%5,%6,%7}, {%8,%9}, {%0,%1,%2,%3};"
        : "+f"(d[0]), "+f"(d[1]), "+f"(d[2]), "+f"(d[3])
        : "r"(a0), "r"(a1), "r"(a2), "r"(a3), "r"(b0), "r"(b1));
}

__device__ __forceinline__ void ldsm4(uint32_t& r0, uint32_t& r1,
                                      uint32_t& r2, uint32_t& r3, uint32_t a) {
    asm volatile("ldmatrix.sync.aligned.m8n8.x4.shared.b16 {%0,%1,%2,%3}, [%4];"
                 : "=r"(r0), "=r"(r1), "=r"(r2), "=r"(r3) : "r"(a));
}

__device__ __forceinline__ uint32_t packbf(__nv_bfloat16 a, __nv_bfloat16 b) {
    __nv_bfloat162 t(a, b);
    return *reinterpret_cast<uint32_t*>(&t);
}

__device__ __forceinline__ uint32_t smem_u32p(const void* p) {
    uint32_t r;
    asm("{ .reg .u64 t; cvta.to.shared.u64 t, %1; cvt.u32.u64 %0, t; }"
        : "=r"(r) : "l"(p));
    return r;
}

__device__ __forceinline__ void cp16(uint32_t dst, const void* src) {
    asm volatile("cp.async.cg.shared.global [%0], [%1], 16;"
                 :: "r"(dst), "l"(src));
}
#define CP_COMMIT() asm volatile("cp.async.commit_group;" ::: "memory")
#define CP_WAIT0()  asm volatile("cp.async.wait_group 0;" ::: "memory")
#define CP_WAIT1()  asm volatile("cp.async.wait_group 1;" ::: "memory")
#define CP_WAIT2()  asm volatile("cp.async.wait_group 2;" ::: "memory")

// K address: quad interleave within 64-float row (validated in R13).
__device__ __forceinline__ size_t kaddr(int m, int n) {
    const int t = m & (TSEQ - 1), d = n & 63;
    const size_t pl = (size_t)(((m >> 11) << 2) + (n >> 6)) * PLANE;
    const int pos = ((d >> 4) << 4) + ((d & 3) << 2) + ((d >> 2) & 3);
    return pl + (size_t)t * 64 + pos;
}
// V address: t-quad interleave (tf32 floats).
__device__ __forceinline__ size_t vaddr(int m, int n) {
    const int t = m & (TSEQ - 1), d = n & 63;
    const size_t pl = (size_t)(((m >> 11) << 2) + (n >> 6)) * PLANE;
    return pl + (size_t)(t >> 4) * 1024 + d * 16 + ((t & 3) << 2) + ((t >> 2) & 3);
}

// ---------------------------------------------------------------------------
// One-shot converters
// ---------------------------------------------------------------------------
__global__ __launch_bounds__(256) void conv_pack(
    const float* __restrict__ A, uint32_t* __restrict__ H,
    uint32_t* __restrict__ L, int n4)
{
    int i = blockIdx.x * blockDim.x + threadIdx.x;
    if (i == 0) g_jobctr = 0;
    if (i >= n4) return;
    float4 v = ((const float4*)A)[i];
    __nv_bfloat16 hx = __float2bfloat16_rn(v.x);
    __nv_bfloat16 hy = __float2bfloat16_rn(v.y);
    __nv_bfloat16 hz = __float2bfloat16_rn(v.z);
    __nv_bfloat16 hw = __float2bfloat16_rn(v.w);
    ((uint2*)H)[i] = make_uint2(packbf(hx, hy), packbf(hz, hw));
    ((uint2*)L)[i] = make_uint2(
        packbf(__float2bfloat16_rn(v.x - __bfloat162float(hx)),
               __float2bfloat16_rn(v.y - __bfloat162float(hy))),
        packbf(__float2bfloat16_rn(v.z - __bfloat162float(hz)),
               __float2bfloat16_rn(v.w - __bfloat162float(hw))));
}

__global__ __launch_bounds__(256) void conv_wT_all(
    const float* __restrict__ Wq, const float* __restrict__ Wk,
    const float* __restrict__ Wv, const float* __restrict__ Wo)
{
    const float* W; uint32_t* H; uint32_t* L; int N;
    switch (blockIdx.z) {
        case 0: W = Wq; H = g_WqTh; L = g_WqTl; N = D_MODEL; break;
        case 1: W = Wk; H = g_WkTh; L = g_WkTl; N = KV_DIM;  break;
        case 2: W = Wv; H = g_WvTh; L = g_WvTl; N = KV_DIM;  break;
        default:W = Wo; H = g_WoTh; L = g_WoTl; N = D_MODEL; break;
    }
    const int n0 = blockIdx.x * 32, k0 = blockIdx.y * 32;
    if (n0 >= N) return;
    __shared__ float t[32][33];
    const int tx = threadIdx.x, ty = threadIdx.y;
#pragma unroll
    for (int i = 0; i < 4; i++)
        t[ty + i * 8][tx] = W[(size_t)(k0 + ty + i * 8) * N + n0 + tx];
    __syncthreads();
#pragma unroll
    for (int i = 0; i < 2; i++) {
        const int kp = ty + i * 8;
        float a = t[kp * 2][tx], b = t[kp * 2 + 1][tx];
        __nv_bfloat16 ha = __float2bfloat16_rn(a);
        __nv_bfloat16 hb = __float2bfloat16_rn(b);
        const size_t o = (size_t)(n0 + tx) * KH2 + k0 / 2 + kp;
        H[o] = packbf(ha, hb);
        L[o] = packbf(__float2bfloat16_rn(a - __bfloat162float(ha)),
                      __float2bfloat16_rn(b - __bfloat162float(hb)));
    }
}

// ---------------------------------------------------------------------------
// 2-term bf16-split GEMM, cp.async double-buffered, ldmatrix fragment loads.
// MODE: 0 = plain fp32; 1 = tf32(premul) row-major (Q);
//       2 = tf32 K quad-interleave; 3 = tf32 V t-quad-interleave.
// ---------------------------------------------------------------------------
#define GROW 20
#define G_AH 0
#define G_AL (128 * GROW)
#define G_BH (2 * 128 * GROW)
#define G_BL (3 * 128 * GROW)
#define G_U32 (4 * 128 * GROW)
#define GEMM_SMEM (2 * G_U32 * 4)

__device__ __forceinline__ void gemm_stage(
    uint32_t sbase, const uint32_t* __restrict__ AH,
    const uint32_t* __restrict__ AL, const uint32_t* __restrict__ BH,
    const uint32_t* __restrict__ BL, int KH, int m0, int n0, int kc2)
{
    const int tid = threadIdx.x;
#pragma unroll
    for (int j = 0; j < 2; j++) {
        const int idx = tid + j * 256;
        const int r = idx >> 2, sg = (idx & 3) * 4;
        const size_t ao = (size_t)(m0 + r) * KH + kc2 + sg;
        const size_t bo = (size_t)(n0 + r) * KH + kc2 + sg;
        const uint32_t d = sbase + (r * GROW + sg) * 4;
        cp16(d + G_AH * 4, AH + ao);
        cp16(d + G_AL * 4, AL + ao);
        cp16(d + G_BH * 4, BH + bo);
        cp16(d + G_BL * 4, BL + bo);
    }
    CP_COMMIT();
}

template <int MODE>
__device__ __forceinline__ void gemm_tile_pk(
    const uint32_t* __restrict__ AH, const uint32_t* __restrict__ AL,
    const uint32_t* __restrict__ BH, const uint32_t* __restrict__ BL,
    const float* __restrict__ bias, float* __restrict__ C,
    int N, int KH, int m0, int n0, float premul)
{
    extern __shared__ uint32_t su[];
    const uint32_t sbase = smem_u32p(su);

    const int tid = threadIdx.x;
    const int lane = tid & 31;
    const int wid = tid >> 5;
    const int wm = (wid >> 2) * 64;
    const int wn = (wid & 3) * 32;
    const int lr = lane >> 2;
    const int lc = lane & 3;
    const int lt = lane >> 3;
    const int lrr = lane & 7;

    const uint32_t aBase = sbase +
        (((wm + (lt & 1) * 8 + lrr) * GROW + (lt >> 1) * 4) << 2);
    const uint32_t bBase = sbase +
        ((G_BH + (wn + (lt >> 1) * 8 + lrr) * GROW + (lt & 1) * 4) << 2);

    float acc[4][4][4];
#pragma unroll
    for (int i = 0; i < 4; i++)
#pragma unroll
        for (int j = 0; j < 4; j++)
#pragma unroll
            for (int k = 0; k < 4; k++) acc[i][j][k] = 0.0f;

    const int NC = KH / 16;
    int buf = 0;

    gemm_stage(sbase, AH, AL, BH, BL, KH, m0, n0, 0);

    for (int c = 0; c < NC; c++) {
        CP_WAIT0();
        __syncthreads();
        if (c + 1 < NC)
            gemm_stage(sbase + (buf ^ 1) * G_U32 * 4,
                       AH, AL, BH, BL, KH, m0, n0, (c + 1) * 16);

        const uint32_t bufo = (uint32_t)buf * G_U32 * 4;
#pragma unroll
        for (int ss = 0; ss < 2; ss++) {
            uint32_t bh[4][2], bl[4][2];
#pragma unroll
            for (int p = 0; p < 2; p++) {
                const uint32_t off = bufo + ((p * 16 * GROW + ss * 8) << 2);
                ldsm4(bh[2 * p][0], bh[2 * p][1], bh[2 * p + 1][0],
                      bh[2 * p + 1][1], bBase + off);
                ldsm4(bl[2 * p][0], bl[2 * p][1], bl[2 * p + 1][0],
                      bl[2 * p + 1][1], bBase + off + ((128 * GROW) << 2));
            }
#pragma unroll
            for (int mt = 0; mt < 4; mt++) {
                const uint32_t off = bufo + ((mt * 16 * GROW + ss * 8) << 2);
                uint32_t ah0, ah1, ah2, ah3, al0, al1, al2, al3;
                ldsm4(ah0, ah1, ah2, ah3, aBase + off);
                ldsm4(al0, al1, al2, al3, aBase + off + ((G_AL) << 2));
#pragma unroll
                for (int nt = 0; nt < 4; nt++) {
                    mma16816(acc[mt][nt], ah0, ah1, ah2, ah3, bh[nt][0], bh[nt][1]);
                    mma16816(acc[mt][nt], ah0, ah1, ah2, ah3, bl[nt][0], bl[nt][1]);
                    mma16816(acc[mt][nt], al0, al1, al2, al3, bh[nt][0], bh[nt][1]);
                }
            }
        }
        buf ^= 1;
    }

#pragma unroll
    for (int nt = 0; nt < 4; nt++) {
        const int n = n0 + wn + nt * 8 + lc * 2;
        const float2 bv = *(const float2*)(bias + n);
#pragma unroll
        for (int mt = 0; mt < 4; mt++) {
            const int m = m0 + wm + mt * 16 + lr;
            if (MODE == 0) {
                *(float2*)(C + (size_t)m * N + n) =
                    make_float2(acc[mt][nt][0] + bv.x, acc[mt][nt][1] + bv.y);
                *(float2*)(C + (size_t)(m + 8) * N + n) =
                    make_float2(acc[mt][nt][2] + bv.x, acc[mt][nt][3] + bv.y);
            } else if (MODE == 1) {
                *(float2*)(C + (size_t)m * N + n) =
                    make_float2(f2tf32((acc[mt][nt][0] + bv.x) * premul),
                                f2tf32((acc[mt][nt][1] + bv.y) * premul));
                *(float2*)(C + (size_t)(m + 8) * N + n) =
                    make_float2(f2tf32((acc[mt][nt][2] + bv.x) * premul),
                                f2tf32((acc[mt][nt][3] + bv.y) * premul));
            } else if (MODE == 2) {
                C[kaddr(m, n)]         = f2tf32(acc[mt][nt][0] + bv.x);
                C[kaddr(m, n + 1)]     = f2tf32(acc[mt][nt][1] + bv.y);
                C[kaddr(m + 8, n)]     = f2tf32(acc[mt][nt][2] + bv.x);
                C[kaddr(m + 8, n + 1)] = f2tf32(acc[mt][nt][3] + bv.y);
            } else {
                C[vaddr(m, n)]         = f2tf32(acc[mt][nt][0] + bv.x);
                C[vaddr(m, n + 1)]     = f2tf32(acc[mt][nt][1] + bv.y);
                C[vaddr(m + 8, n)]     = f2tf32(acc[mt][nt][2] + bv.x);
                C[vaddr(m + 8, n + 1)] = f2tf32(acc[mt][nt][3] + bv.y);
            }
        }
    }
}

__global__ __launch_bounds__(256, 2) void gemm_qkv(
    const float* __restrict__ bq, const float* __restrict__ bk,
    const float* __restrict__ bv,
    float* __restrict__ Q, float* __restrict__ K, float* __restrict__ V)
{
    const int col0 = blockIdx.x * 128;
    const int m0 = blockIdx.y * 128;
    if (col0 < D_MODEL) {
        gemm_tile_pk<1>(g_xh, g_xl, g_WqTh, g_WqTl, bq, Q, D_MODEL, KH2,
                        m0, col0, QSCALE);
    } else if (col0 < D_MODEL + KV_DIM) {
        gemm_tile_pk<2>(g_xh, g_xl, g_WkTh, g_WkTl, bk, K, KV_DIM, KH2,
                        m0, col0 - D_MODEL, 1.0f);
    } else {
        gemm_tile_pk<3>(g_xh, g_xl, g_WvTh, g_WvTl, bv, V, KV_DIM, KH2,
                        m0, col0 - D_MODEL - KV_DIM, 1.0f);
    }
}

__global__ __launch_bounds__(256, 2) void gemm_o(
    const float* __restrict__ bias, float* __restrict__ C)
{
    gemm_tile_pk<0>(g_Oh, g_Ol, g_WoTh, g_WoTl, bias, C, D_MODEL, KH2,
                    blockIdx.y * 128, blockIdx.x * 128, 1.0f);
}

// ---------------------------------------------------------------------------
// Causal GQA flash attention (tf32 mma.sync throughout — R12 numerics).
// K and V both quad-interleaved in GMEM: every B-fragment pair of loads is
// one LDS.128 feeding two k8 MMAs. P round-trips through smem (warp-local).
// Persistent CTAs with dynamic job scheduling.
// ---------------------------------------------------------------------------
#define PS_ST 68
#define KS_ST 80                        // 64 payload + 16 pad: LDS.128 clean
#define OFF_KS (128 * PS_ST)            // 8704 floats
#define KS_BUF (64 * KS_ST)             // 5120
#define OFF_VS (OFF_KS + 2 * KS_BUF)    // 18944
#define VS_BUF 4096                     // 64 t x 64 d floats (quad layout)
#define ATTN_SMEM ((OFF_VS + 2 * VS_BUF) * 4)   // 108544 B

__global__ __launch_bounds__(256, 2) void attn_mma()
{
    extern __shared__ float sm[];
    const uint32_t sbase = smem_u32p(sm);
    float* Ps = sm;                     // Q staging + P buffer
    __shared__ int sjob;

    const int tid = threadIdx.x;
    const int lane = tid & 31;
    const int w = tid >> 5;
    const int lr = lane >> 2;
    const int lc = lane & 3;
    const int r0 = w * 16 + lr;

    for (;;) {
        __syncthreads();
        if (tid == 0) sjob = atomicAdd(&g_jobctr, 1);
        __syncthreads();
        const int job = sjob;
        if (job >= N_JOBS) break;

        const int qt = 15 - (job >> 5);
        const int h = job & 15;
        const int b = (job >> 4) & 1;
        const int g = h >> 2;
        const int tb = b * TSEQ;
        const int nkt = 2 * qt + 2;
        const float* kbase = g_Kp + (size_t)(b * 4 + g) * PLANE;
        const float* vbase = g_Vp + (size_t)(b * 4 + g) * PLANE;

        auto stage_kv = [&](int kt) {
            const int bf = kt & 1;
            // K: 64 keys x 64 floats (quad layout), contiguous per key.
            const int krow = tid >> 2, kseg = (tid & 3) * 16;
            const float* kr = kbase + (size_t)(kt * 64 + krow) * 64 + kseg;
            const uint32_t kd = sbase + (OFF_KS + bf * KS_BUF + krow * KS_ST + kseg) * 4;
#pragma unroll
            for (int i = 0; i < 4; i++) cp16(kd + i * 16, kr + i * 4);
            // V: 4096 contiguous floats per tile (quad layout preserved).
            const float* vr = vbase + (size_t)kt * 4096 + tid * 16;
            const uint32_t vd = sbase + (OFF_VS + bf * VS_BUF + tid * 16) * 4;
#pragma unroll
            for (int i = 0; i < 4; i++) cp16(vd + i * 16, vr + i * 4);
            CP_COMMIT();
        };

        // Q tile via cp.async (pre-scaled + tf32-rounded by gemm_qkv).
        {
            const int r = tid >> 1, c0 = (tid & 1) * 32;
            const float* qr = g_Q + (size_t)(tb + qt * 128 + r) * D_MODEL
                              + h * HEAD_DIM + c0;
            const uint32_t d = sbase + (r * PS_ST + c0) * 4;
#pragma unroll
            for (int i = 0; i < 8; i++) cp16(d + i * 16, qr + i * 4);
            CP_COMMIT();
        }
        stage_kv(0);
        stage_kv(1);
        CP_WAIT2();
        __syncthreads();

        float qf[8][4];
#pragma unroll
        for (int kb8 = 0; kb8 < 8; kb8++) {
            const float* q0 = Ps + r0 * PS_ST + kb8 * 8 + lc;
            qf[kb8][0] = q0[0];
            qf[kb8][1] = q0[8 * PS_ST];
            qf[kb8][2] = q0[4];
            qf[kb8][3] = q0[8 * PS_ST + 4];
        }

        float oacc[8][4];
#pragma unroll
        for (int nt = 0; nt < 8; nt++)
#pragma unroll
            for (int j = 0; j < 4; j++) oacc[nt][j] = 0.0f;
        float m0 = -1e30f, m1 = -1e30f, l0 = 0.0f, l1 = 0.0f;

        const int qi0 = qt * 128 + r0;
        const int qi1 = qi0 + 8;

        for (int kt = 0; kt < nkt; kt++) {
            if (kt + 1 < nkt) { CP_WAIT1(); } else { CP_WAIT0(); }
            __syncthreads();
            const float* Ks = sm + OFF_KS + (kt & 1) * KS_BUF;
            const float* Vs = sm + OFF_VS + (kt & 1) * VS_BUF;

            // S = Q @ K^T : one LDS.128 feeds two k8 MMAs.
            float sa[8][4];
#pragma unroll
            for (int nt = 0; nt < 8; nt++)
#pragma unroll
                for (int j = 0; j < 4; j++) sa[nt][j] = 0.0f;
#pragma unroll
            for (int kb16 = 0; kb16 < 4; kb16++) {
#pragma unroll
                for (int nt = 0; nt < 8; nt++) {
                    const float4 kk = *(const float4*)(Ks +
                        (nt * 8 + lr) * KS_ST + kb16 * 16 + lc * 4);
                    mma1688(sa[nt], qf[2 * kb16][0], qf[2 * kb16][1],
                            qf[2 * kb16][2], qf[2 * kb16][3], kk.x, kk.y);
                    mma1688(sa[nt], qf[2 * kb16 + 1][0], qf[2 * kb16 + 1][1],
                            qf[2 * kb16 + 1][2], qf[2 * kb16 + 1][3], kk.z, kk.w);
                }
            }

            if (kt >= 2 * qt) {
#pragma unroll
                for (int nt = 0; nt < 8; nt++) {
                    const int kj = kt * 64 + nt * 8 + 2 * lc;
                    if (kj > qi0)     sa[nt][0] = -1e30f;
                    if (kj + 1 > qi0) sa[nt][1] = -1e30f;
                    if (kj > qi1)     sa[nt][2] = -1e30f;
                    if (kj + 1 > qi1) sa[nt][3] = -1e30f;
                }
            }

            // Online softmax (log2 domain).
            float mx0 = sa[0][0], mx1 = sa[0][2];
#pragma unroll
            for (int nt = 0; nt < 8; nt++) {
                mx0 = fmaxf(mx0, fmaxf(sa[nt][0], sa[nt][1]));
                mx1 = fmaxf(mx1, fmaxf(sa[nt][2], sa[nt][3]));
            }
            mx0 = fmaxf(mx0, __shfl_xor_sync(0xffffffffu, mx0, 1));
            mx0 = fmaxf(mx0, __shfl_xor_sync(0xffffffffu, mx0, 2));
            mx1 = fmaxf(mx1, __shfl_xor_sync(0xffffffffu, mx1, 1));
            mx1 = fmaxf(mx1, __shfl_xor_sync(0xffffffffu, mx1, 2));
            const float nm0 = fmaxf(m0, mx0), nm1 = fmaxf(m1, mx1);
            const float cf0 = exp2f(m0 - nm0), cf1 = exp2f(m1 - nm1);
            m0 = nm0; m1 = nm1;
            float rs0 = 0.0f, rs1 = 0.0f;
#pragma unroll
            for (int nt = 0; nt < 8; nt++) {
                float p0 = exp2f(sa[nt][0] - nm0);
                float p1 = exp2f(sa[nt][1] - nm0);
                float p2 = exp2f(sa[nt][2] - nm1);
                float p3 = exp2f(sa[nt][3] - nm1);
                rs0 += p0 + p1; rs1 += p2 + p3;
                sa[nt][0] = f2tf32(p0); sa[nt][1] = f2tf32(p1);
                sa[nt][2] = f2tf32(p2); sa[nt][3] = f2tf32(p3);
            }
            rs0 += __shfl_xor_sync(0xffffffffu, rs0, 1);
            rs0 += __shfl_xor_sync(0xffffffffu, rs0, 2);
            rs1 += __shfl_xor_sync(0xffffffffu, rs1, 1);
            rs1 += __shfl_xor_sync(0xffffffffu, rs1, 2);
            l0 = l0 * cf0 + rs0;
            l1 = l1 * cf1 + rs1;
#pragma unroll
            for (int nt = 0; nt < 8; nt++) {
                oacc[nt][0] *= cf0; oacc[nt][1] *= cf0;
                oacc[nt][2] *= cf1; oacc[nt][3] *= cf1;
            }

            // P -> smem (warp-local rows), then O += P @ V.
#pragma unroll
            for (int nt = 0; nt < 8; nt++) {
                *(float2*)(Ps + r0 * PS_ST + nt * 8 + 2 * lc) =
                    make_float2(sa[nt][0], sa[nt][1]);
                *(float2*)(Ps + (r0 + 8) * PS_ST + nt * 8 + 2 * lc) =
                    make_float2(sa[nt][2], sa[nt][3]);
            }
            __syncwarp();

            // O += P @ V : one LDS.128 feeds two k8 MMAs.
#pragma unroll
            for (int kb16 = 0; kb16 < 4; kb16++) {
                const float* prA = Ps + r0 * PS_ST + kb16 * 16 + lc;
                const float a0 = prA[0];
                const float a1 = prA[8 * PS_ST];
                const float a2 = prA[4];
                const float a3 = prA[8 * PS_ST + 4];
                const float* prB = prA + 8;
                const float b0 = prB[0];
                const float b1 = prB[8 * PS_ST];
                const float b2 = prB[4];
                const float b3 = prB[8 * PS_ST + 4];
#pragma unroll
                for (int nt = 0; nt < 8; nt++) {
                    const float4 vv = *(const float4*)(Vs +
                        kb16 * 1024 + (nt * 8 + lr) * 16 + lc * 4);
                    mma1688(oacc[nt], a0, a1, a2, a3, vv.x, vv.y);
                    mma1688(oacc[nt], b0, b1, b2, b3, vv.z, vv.w);
                }
            }
            __syncthreads();
            if (kt + 2 < nkt) stage_kv(kt + 2);
        }

        // Normalize; write packed bf16x2 hi/lo (feeds gemm_o).
        const float inv0 = 1.0f / l0, inv1 = 1.0f / l1;
        const size_t row0 = (size_t)(tb + qt * 128 + r0);
        const int colp = h * 32 + lc;
#pragma unroll
        for (int nt = 0; nt < 8; nt++) {
            float v0 = oacc[nt][0] * inv0, v1 = oacc[nt][1] * inv0;
            float v2 = oacc[nt][2] * inv1, v3 = oacc[nt][3] * inv1;
            __nv_bfloat16 h0 = __float2bfloat16_rn(v0);
            __nv_bfloat16 h1 = __float2bfloat16_rn(v1);
            __nv_bfloat16 h2 = __float2bfloat16_rn(v2);
            __nv_bfloat16 h3 = __float2bfloat16_rn(v3);
            const size_t o0 = row0 * KH2 + colp + nt * 4;
            const size_t o1 = (row0 + 8) * KH2 + colp + nt * 4;
            g_Oh[o0] = packbf(h0, h1);
            g_Ol[o0] = packbf(__float2bfloat16_rn(v0 - __bfloat162float(h0)),
                              __float2bfloat16_rn(v1 - __bfloat162float(h1)));
            g_Oh[o1] = packbf(h2, h3);
            g_Ol[o1] = packbf(__float2bfloat16_rn(v2 - __bfloat162float(h2)),
                              __float2bfloat16_rn(v3 - __bfloat162float(h3)));
        }
    }
}

// ---------------------------------------------------------------------------
extern "C" void kernel_launch(void* const* d_in, const int* in_sizes, int n_in,
                              void* d_out, int out_size)
{
    const float* x  = (const float*)d_in[0];
    const float* Wq = (const float*)d_in[1];
    const float* bq = (const float*)d_in[2];
    const float* Wk = (const float*)d_in[3];
    const float* bk = (const float*)d_in[4];
    const float* Wv = (const float*)d_in[5];
    const float* bv = (const float*)d_in[6];
    const float* Wo = (const float*)d_in[7];
    const float* bo = (const float*)d_in[8];
    float* out = (float*)d_out;

    float *Qp, *Kp, *Vp;
    uint32_t *xh, *xl;
    cudaGetSymbolAddress((void**)&Qp, g_Q);
    cudaGetSymbolAddress((void**)&Kp, g_Kp);
    cudaGetSymbolAddress((void**)&Vp, g_Vp);
    cudaGetSymbolAddress((void**)&xh, g_xh);
    cudaGetSymbolAddress((void**)&xl, g_xl);

    cudaFuncSetAttribute(gemm_qkv, cudaFuncAttributeMaxDynamicSharedMemorySize, GEMM_SMEM);
    cudaFuncSetAttribute(gemm_o,   cudaFuncAttributeMaxDynamicSharedMemorySize, GEMM_SMEM);
    cudaFuncSetAttribute(attn_mma, cudaFuncAttributeMaxDynamicSharedMemorySize, ATTN_SMEM);

    // One-shot conversions (+ job counter reset inside conv_pack).
    conv_pack<<<(BT * D_MODEL / 4 + 255) / 256, 256>>>(x, xh, xl, BT * D_MODEL / 4);
    conv_wT_all<<<dim3(D_MODEL / 32, D_MODEL / 32, 4), dim3(32, 8)>>>(Wq, Wk, Wv, Wo);

    // Fused QKV projection (Q tf32+scaled; K tf32 d-quads; V tf32 t-quads).
    gemm_qkv<<<dim3((D_MODEL + 2 * KV_DIM) / 128, BT / 128), 256, GEMM_SMEM>>>(
        bq, bk, bv, Qp, Kp, Vp);

    // Causal GQA attention (persistent CTAs, dynamic job scheduling).
    attn_mma<<<304, 256, ATTN_SMEM>>>();

    // Output projection.
    gemm_o<<<dim3(D_MODEL / 128, BT / 128), 256, GEMM_SMEM>>>(bo, out);
}

// round 15
// speedup vs baseline: 1.4172x; 1.0441x over previous
#include <cuda_runtime.h>
#include <cuda_bf16.h>
#include <cstdint>

#define D_MODEL 1024
#define KV_DIM 256
#define N_HEADS 16
#define HEAD_DIM 64
#define TSEQ 2048
#define BATCH 2
#define BT (BATCH * TSEQ)
#define KH2 (D_MODEL / 2)
#define QSCALE (0.125f * 1.4426950408889634f)   // 1/sqrt(64) * log2(e)
#define N_JOBS (16 * N_HEADS * BATCH)           // 512 attention tile-jobs
#define PLANE (TSEQ * HEAD_DIM)                 // 131072 floats per (b,g)

// Scratch (device globals; no allocation anywhere).
__device__ float g_Q[(size_t)BT * D_MODEL];
// K quad-interleaved: plane(b,g) -> [t][pos(d)], pos = (d>>4)*16+(d&3)*4+((d>>2)&3)
__device__ float g_Kp[(size_t)BT * KV_DIM];
// V t-quad-interleaved (tf32): plane(b,g) ->
//   [blk=t>>4][d][(t&3)*4 + ((t>>2)&3)]   (blk stride 1024, d stride 16)
__device__ float g_Vp[(size_t)BT * KV_DIM];
__device__ int g_jobctr;
// packed bf16x2 hi/lo operands
__device__ uint32_t g_xh[(size_t)BT * KH2];
__device__ uint32_t g_xl[(size_t)BT * KH2];
__device__ uint32_t g_Oh[(size_t)BT * KH2];
__device__ uint32_t g_Ol[(size_t)BT * KH2];
__device__ uint32_t g_WqTh[(size_t)D_MODEL * KH2];
__device__ uint32_t g_WqTl[(size_t)D_MODEL * KH2];
__device__ uint32_t g_WkTh[(size_t)KV_DIM * KH2];
__device__ uint32_t g_WkTl[(size_t)KV_DIM * KH2];
__device__ uint32_t g_WvTh[(size_t)KV_DIM * KH2];
__device__ uint32_t g_WvTl[(size_t)KV_DIM * KH2];
__device__ uint32_t g_WoTh[(size_t)D_MODEL * KH2];
__device__ uint32_t g_WoTl[(size_t)D_MODEL * KH2];

// ---------------------------------------------------------------------------
// Helpers
// ---------------------------------------------------------------------------
__device__ __forceinline__ float f2tf32(float v) {
    uint32_t u; asm("cvt.rna.tf32.f32 %0, %1;" : "=r"(u) : "f"(v));
    return __uint_as_float(u);
}

__device__ __forceinline__ void mma1688(float* d, float a0, float a1, float a2,
                                        float a3, float b0, float b1) {
    asm volatile(
        "mma.sync.aligned.m16n8k8.row.col.f32.tf32.tf32.f32 "
        "{%0,%1,%2,%3}, {%4,%5,%6,%7}, {%8,%9}, {%0,%1,%2,%3};"
        : "+f"(d[0]), "+f"(d[1]), "+f"(d[2]), "+f"(d[3])
        : "r"(__float_as_uint(a0)), "r"(__float_as_uint(a1)),
          "r"(__float_as_uint(a2)), "r"(__float_as_uint(a3)),
          "r"(__float_as_uint(b0)), "r"(__float_as_uint(b1)));
}

__device__ __forceinline__ void mma16816(float* d, uint32_t a0, uint32_t a1,
                                         uint32_t a2, uint32_t a3,
                                         uint32_t b0, uint32_t b1) {
    asm volatile(
        "mma.sync.aligned.m16n8k16.row.col.f32.bf16.bf16.f32 "
        "{%0,%1,%2,%3}, {%4,%5,%6,%7}, {%8,%9}, {%0,%1,%2,%3};"
        : "+f"(d[0]), "+f"(d[1]), "+f"(d[2]), "+f"(d[3])
        : "r"(a0), "r"(a1), "r"(a2), "r"(a3), "r"(b0), "r"(b1));
}

__device__ __forceinline__ void ldsm4(uint32_t& r0, uint32_t& r1,
                                      uint32_t& r2, uint32_t& r3, uint32_t a) {
    asm volatile("ldmatrix.sync.aligned.m8n8.x4.shared.b16 {%0,%1,%2,%3}, [%4];"
                 : "=r"(r0), "=r"(r1), "=r"(r2), "=r"(r3) : "r"(a));
}

__device__ __forceinline__ uint32_t packbf(__nv_bfloat16 a, __nv_bfloat16 b) {
    __nv_bfloat162 t(a, b);
    return *reinterpret_cast<uint32_t*>(&t);
}

__device__ __forceinline__ uint32_t smem_u32p(const void* p) {
    uint32_t r;
    asm("{ .reg .u64 t; cvta.to.shared.u64 t, %1; cvt.u32.u64 %0, t; }"
        : "=r"(r) : "l"(p));
    return r;
}

__device__ __forceinline__ void cp16(uint32_t dst, const void* src) {
    asm volatile("cp.async.cg.shared.global [%0], [%1], 16;"
                 :: "r"(dst), "l"(src));
}
#define CP_COMMIT() asm volatile("cp.async.commit_group;" ::: "memory")
#define CP_WAIT0()  asm volatile("cp.async.wait_group 0;" ::: "memory")
#define CP_WAIT1()  asm volatile("cp.async.wait_group 1;" ::: "memory")

// K address: quad interleave within 64-float row.
__device__ __forceinline__ size_t kaddr(int m, int n) {
    const int t = m & (TSEQ - 1), d = n & 63;
    const size_t pl = (size_t)(((m >> 11) << 2) + (n >> 6)) * PLANE;
    const int pos = ((d >> 4) << 4) + ((d & 3) << 2) + ((d >> 2) & 3);
    return pl + (size_t)t * 64 + pos;
}
// V address: t-quad interleave (tf32 floats).
__device__ __forceinline__ size_t vaddr(int m, int n) {
    const int t = m & (TSEQ - 1), d = n & 63;
    const size_t pl = (size_t)(((m >> 11) << 2) + (n >> 6)) * PLANE;
    return pl + (size_t)(t >> 4) * 1024 + d * 16 + ((t & 3) << 2) + ((t >> 2) & 3);
}

// ---------------------------------------------------------------------------
// One-shot converters
// ---------------------------------------------------------------------------
__global__ __launch_bounds__(256) void conv_pack(
    const float* __restrict__ A, uint32_t* __restrict__ H,
    uint32_t* __restrict__ L, int n4)
{
    int i = blockIdx.x * blockDim.x + threadIdx.x;
    if (i == 0) g_jobctr = 0;
    if (i >= n4) return;
    float4 v = ((const float4*)A)[i];
    __nv_bfloat16 hx = __float2bfloat16_rn(v.x);
    __nv_bfloat16 hy = __float2bfloat16_rn(v.y);
    __nv_bfloat16 hz = __float2bfloat16_rn(v.z);
    __nv_bfloat16 hw = __float2bfloat16_rn(v.w);
    ((uint2*)H)[i] = make_uint2(packbf(hx, hy), packbf(hz, hw));
    ((uint2*)L)[i] = make_uint2(
        packbf(__float2bfloat16_rn(v.x - __bfloat162float(hx)),
               __float2bfloat16_rn(v.y - __bfloat162float(hy))),
        packbf(__float2bfloat16_rn(v.z - __bfloat162float(hz)),
               __float2bfloat16_rn(v.w - __bfloat162float(hw))));
}

__global__ __launch_bounds__(256) void conv_wT_all(
    const float* __restrict__ Wq, const float* __restrict__ Wk,
    const float* __restrict__ Wv, const float* __restrict__ Wo)
{
    const float* W; uint32_t* H; uint32_t* L; int N;
    switch (blockIdx.z) {
        case 0: W = Wq; H = g_WqTh; L = g_WqTl; N = D_MODEL; break;
        case 1: W = Wk; H = g_WkTh; L = g_WkTl; N = KV_DIM;  break;
        case 2: W = Wv; H = g_WvTh; L = g_WvTl; N = KV_DIM;  break;
        default:W = Wo; H = g_WoTh; L = g_WoTl; N = D_MODEL; break;
    }
    const int n0 = blockIdx.x * 32, k0 = blockIdx.y * 32;
    if (n0 >= N) return;
    __shared__ float t[32][33];
    const int tx = threadIdx.x, ty = threadIdx.y;
#pragma unroll
    for (int i = 0; i < 4; i++)
        t[ty + i * 8][tx] = W[(size_t)(k0 + ty + i * 8) * N + n0 + tx];
    __syncthreads();
#pragma unroll
    for (int i = 0; i < 2; i++) {
        const int kp = ty + i * 8;
        float a = t[kp * 2][tx], b = t[kp * 2 + 1][tx];
        __nv_bfloat16 ha = __float2bfloat16_rn(a);
        __nv_bfloat16 hb = __float2bfloat16_rn(b);
        const size_t o = (size_t)(n0 + tx) * KH2 + k0 / 2 + kp;
        H[o] = packbf(ha, hb);
        L[o] = packbf(__float2bfloat16_rn(a - __bfloat162float(ha)),
                      __float2bfloat16_rn(b - __bfloat162float(hb)));
    }
}

// ---------------------------------------------------------------------------
// 2-term bf16-split GEMM, cp.async double-buffered, ldmatrix fragment loads.
// MODE: 0 = plain fp32; 1 = tf32(premul) row-major (Q);
//       2 = tf32 K quad-interleave; 3 = tf32 V t-quad-interleave.
// ---------------------------------------------------------------------------
#define GROW 20
#define G_AH 0
#define G_AL (128 * GROW)
#define G_BH (2 * 128 * GROW)
#define G_BL (3 * 128 * GROW)
#define G_U32 (4 * 128 * GROW)
#define GEMM_SMEM (2 * G_U32 * 4)

__device__ __forceinline__ void gemm_stage(
    uint32_t sbase, const uint32_t* __restrict__ AH,
    const uint32_t* __restrict__ AL, const uint32_t* __restrict__ BH,
    const uint32_t* __restrict__ BL, int KH, int m0, int n0, int kc2)
{
    const int tid = threadIdx.x;
#pragma unroll
    for (int j = 0; j < 2; j++) {
        const int idx = tid + j * 256;
        const int r = idx >> 2, sg = (idx & 3) * 4;
        const size_t ao = (size_t)(m0 + r) * KH + kc2 + sg;
        const size_t bo = (size_t)(n0 + r) * KH + kc2 + sg;
        const uint32_t d = sbase + (r * GROW + sg) * 4;
        cp16(d + G_AH * 4, AH + ao);
        cp16(d + G_AL * 4, AL + ao);
        cp16(d + G_BH * 4, BH + bo);
        cp16(d + G_BL * 4, BL + bo);
    }
    CP_COMMIT();
}

template <int MODE>
__device__ __forceinline__ void gemm_tile_pk(
    const uint32_t* __restrict__ AH, const uint32_t* __restrict__ AL,
    const uint32_t* __restrict__ BH, const uint32_t* __restrict__ BL,
    const float* __restrict__ bias, float* __restrict__ C,
    int N, int KH, int m0, int n0, float premul)
{
    extern __shared__ uint32_t su[];
    const uint32_t sbase = smem_u32p(su);

    const int tid = threadIdx.x;
    const int lane = tid & 31;
    const int wid = tid >> 5;
    const int wm = (wid >> 2) * 64;
    const int wn = (wid & 3) * 32;
    const int lr = lane >> 2;
    const int lc = lane & 3;
    const int lt = lane >> 3;
    const int lrr = lane & 7;

    const uint32_t aBase = sbase +
        (((wm + (lt & 1) * 8 + lrr) * GROW + (lt >> 1) * 4) << 2);
    const uint32_t bBase = sbase +
        ((G_BH + (wn + (lt >> 1) * 8 + lrr) * GROW + (lt & 1) * 4) << 2);

    float acc[4][4][4];
#pragma unroll
    for (int i = 0; i < 4; i++)
#pragma unroll
        for (int j = 0; j < 4; j++)
#pragma unroll
            for (int k = 0; k < 4; k++) acc[i][j][k] = 0.0f;

    const int NC = KH / 16;
    int buf = 0;

    gemm_stage(sbase, AH, AL, BH, BL, KH, m0, n0, 0);

    for (int c = 0; c < NC; c++) {
        CP_WAIT0();
        __syncthreads();
        if (c + 1 < NC)
            gemm_stage(sbase + (buf ^ 1) * G_U32 * 4,
                       AH, AL, BH, BL, KH, m0, n0, (c + 1) * 16);

        const uint32_t bufo = (uint32_t)buf * G_U32 * 4;
#pragma unroll
        for (int ss = 0; ss < 2; ss++) {
            uint32_t bh[4][2], bl[4][2];
#pragma unroll
            for (int p = 0; p < 2; p++) {
                const uint32_t off = bufo + ((p * 16 * GROW + ss * 8) << 2);
                ldsm4(bh[2 * p][0], bh[2 * p][1], bh[2 * p + 1][0],
                      bh[2 * p + 1][1], bBase + off);
                ldsm4(bl[2 * p][0], bl[2 * p][1], bl[2 * p + 1][0],
                      bl[2 * p + 1][1], bBase + off + ((128 * GROW) << 2));
            }
#pragma unroll
            for (int mt = 0; mt < 4; mt++) {
                const uint32_t off = bufo + ((mt * 16 * GROW + ss * 8) << 2);
                uint32_t ah0, ah1, ah2, ah3, al0, al1, al2, al3;
                ldsm4(ah0, ah1, ah2, ah3, aBase + off);
                ldsm4(al0, al1, al2, al3, aBase + off + ((G_AL) << 2));
#pragma unroll
                for (int nt = 0; nt < 4; nt++) {
                    mma16816(acc[mt][nt], ah0, ah1, ah2, ah3, bh[nt][0], bh[nt][1]);
                    mma16816(acc[mt][nt], ah0, ah1, ah2, ah3, bl[nt][0], bl[nt][1]);
                    mma16816(acc[mt][nt], al0, al1, al2, al3, bh[nt][0], bh[nt][1]);
                }
            }
        }
        buf ^= 1;
    }

#pragma unroll
    for (int nt = 0; nt < 4; nt++) {
        const int n = n0 + wn + nt * 8 + lc * 2;
        const float2 bv = *(const float2*)(bias + n);
#pragma unroll
        for (int mt = 0; mt < 4; mt++) {
            const int m = m0 + wm + mt * 16 + lr;
            if (MODE == 0) {
                *(float2*)(C + (size_t)m * N + n) =
                    make_float2(acc[mt][nt][0] + bv.x, acc[mt][nt][1] + bv.y);
                *(float2*)(C + (size_t)(m + 8) * N + n) =
                    make_float2(acc[mt][nt][2] + bv.x, acc[mt][nt][3] + bv.y);
            } else if (MODE == 1) {
                *(float2*)(C + (size_t)m * N + n) =
                    make_float2(f2tf32((acc[mt][nt][0] + bv.x) * premul),
                                f2tf32((acc[mt][nt][1] + bv.y) * premul));
                *(float2*)(C + (size_t)(m + 8) * N + n) =
                    make_float2(f2tf32((acc[mt][nt][2] + bv.x) * premul),
                                f2tf32((acc[mt][nt][3] + bv.y) * premul));
            } else if (MODE == 2) {
                C[kaddr(m, n)]         = f2tf32(acc[mt][nt][0] + bv.x);
                C[kaddr(m, n + 1)]     = f2tf32(acc[mt][nt][1] + bv.y);
                C[kaddr(m + 8, n)]     = f2tf32(acc[mt][nt][2] + bv.x);
                C[kaddr(m + 8, n + 1)] = f2tf32(acc[mt][nt][3] + bv.y);
            } else {
                C[vaddr(m, n)]         = f2tf32(acc[mt][nt][0] + bv.x);
                C[vaddr(m, n + 1)]     = f2tf32(acc[mt][nt][1] + bv.y);
                C[vaddr(m + 8, n)]     = f2tf32(acc[mt][nt][2] + bv.x);
                C[vaddr(m + 8, n + 1)] = f2tf32(acc[mt][nt][3] + bv.y);
            }
        }
    }
}

__global__ __launch_bounds__(256, 2) void gemm_qkv(
    const float* __restrict__ bq, const float* __restrict__ bk,
    const float* __restrict__ bv,
    float* __restrict__ Q, float* __restrict__ K, float* __restrict__ V)
{
    const int col0 = blockIdx.x * 128;
    const int m0 = blockIdx.y * 128;
    if (col0 < D_MODEL) {
        gemm_tile_pk<1>(g_xh, g_xl, g_WqTh, g_WqTl, bq, Q, D_MODEL, KH2,
                        m0, col0, QSCALE);
    } else if (col0 < D_MODEL + KV_DIM) {
        gemm_tile_pk<2>(g_xh, g_xl, g_WkTh, g_WkTl, bk, K, KV_DIM, KH2,
                        m0, col0 - D_MODEL, 1.0f);
    } else {
        gemm_tile_pk<3>(g_xh, g_xl, g_WvTh, g_WvTl, bv, V, KV_DIM, KH2,
                        m0, col0 - D_MODEL - KV_DIM, 1.0f);
    }
}

__global__ __launch_bounds__(256, 2) void gemm_o(
    const float* __restrict__ bias, float* __restrict__ C)
{
    gemm_tile_pk<0>(g_Oh, g_Ol, g_WoTh, g_WoTl, bias, C, D_MODEL, KH2,
                    blockIdx.y * 128, blockIdx.x * 128, 1.0f);
}

// ---------------------------------------------------------------------------
// Causal GQA flash attention (tf32 mma.sync, R12/R14 numerics).
// - Q fragments loaded ONCE per job via LDG (no Q smem).
// - P never touches smem: S C-fragments -> PV A-fragments via quad shuffles.
// - K/V triple-buffered: exactly ONE __syncthreads per iteration.
// ---------------------------------------------------------------------------
#define KS_ST 80                        // 64 payload + 16 pad: LDS.128 clean
#define KS_BUF (64 * KS_ST)             // 5120 floats
#define OFF_VS (3 * KS_BUF)             // 15360
#define VS_BUF 4096                     // 64 t x 64 d floats (quad layout)
#define ATTN_SMEM ((OFF_VS + 3 * VS_BUF) * 4)   // 110592 B

// Transform one k8 C-fragment of S into a PV A-fragment (intra-quad shuffles).
#define XFORM(sa_j, A0, A1, A2, A3) do {                                      \
    const int _s0 = (lane & 28) | (lc >> 1);                                  \
    const float _t0 = __shfl_sync(0xffffffffu, (sa_j)[0], _s0);               \
    const float _t1 = __shfl_sync(0xffffffffu, (sa_j)[1], _s0);               \
    const float _u0 = __shfl_sync(0xffffffffu, (sa_j)[2], _s0);               \
    const float _u1 = __shfl_sync(0xffffffffu, (sa_j)[3], _s0);               \
    const float _t2 = __shfl_sync(0xffffffffu, (sa_j)[0], _s0 + 2);           \
    const float _t3 = __shfl_sync(0xffffffffu, (sa_j)[1], _s0 + 2);           \
    const float _u2 = __shfl_sync(0xffffffffu, (sa_j)[2], _s0 + 2);           \
    const float _u3 = __shfl_sync(0xffffffffu, (sa_j)[3], _s0 + 2);           \
    A0 = (lc & 1) ? _t1 : _t0;                                                \
    A1 = (lc & 1) ? _u1 : _u0;                                                \
    A2 = (lc & 1) ? _t3 : _t2;                                                \
    A3 = (lc & 1) ? _u3 : _u2;                                                \
} while (0)

__global__ __launch_bounds__(256, 2) void attn_mma()
{
    extern __shared__ float sm[];
    const uint32_t sbase = smem_u32p(sm);
    __shared__ int sjob;

    const int tid = threadIdx.x;
    const int lane = tid & 31;
    const int w = tid >> 5;
    const int lr = lane >> 2;
    const int lc = lane & 3;
    const int r0 = w * 16 + lr;

    for (;;) {
        __syncthreads();
        if (tid == 0) sjob = atomicAdd(&g_jobctr, 1);
        __syncthreads();
        const int job = sjob;
        if (job >= N_JOBS) break;

        const int qt = 15 - (job >> 5);
        const int h = job & 15;
        const int b = (job >> 4) & 1;
        const int g = h >> 2;
        const int tb = b * TSEQ;
        const int nkt = 2 * qt + 2;
        const float* kbase = g_Kp + (size_t)(b * 4 + g) * PLANE;
        const float* vbase = g_Vp + (size_t)(b * 4 + g) * PLANE;

        auto stage_kv = [&](int kt) {
            const int bf = kt % 3;
            const int krow = tid >> 2, kseg = (tid & 3) * 16;
            const float* kr = kbase + (size_t)(kt * 64 + krow) * 64 + kseg;
            const uint32_t kd = sbase + (bf * KS_BUF + krow * KS_ST + kseg) * 4;
#pragma unroll
            for (int i = 0; i < 4; i++) cp16(kd + i * 16, kr + i * 4);
            const float* vr = vbase + (size_t)kt * 4096 + tid * 16;
            const uint32_t vd = sbase + (OFF_VS + bf * VS_BUF + tid * 16) * 4;
#pragma unroll
            for (int i = 0; i < 4; i++) cp16(vd + i * 16, vr + i * 4);
            CP_COMMIT();
        };

        stage_kv(0);
        stage_kv(1);

        // Q fragments via direct LDG (pre-scaled + tf32-rounded by gemm_qkv).
        float qf[8][4];
        {
            const float* q0 = g_Q + (size_t)(tb + qt * 128 + r0) * D_MODEL
                              + h * HEAD_DIM;
            const float* q1 = q0 + 8 * D_MODEL;
#pragma unroll
            for (int kb8 = 0; kb8 < 8; kb8++) {
                qf[kb8][0] = q0[kb8 * 8 + lc];
                qf[kb8][1] = q1[kb8 * 8 + lc];
                qf[kb8][2] = q0[kb8 * 8 + lc + 4];
                qf[kb8][3] = q1[kb8 * 8 + lc + 4];
            }
        }

        float oacc[8][4];
#pragma unroll
        for (int nt = 0; nt < 8; nt++)
#pragma unroll
            for (int j = 0; j < 4; j++) oacc[nt][j] = 0.0f;
        float m0 = -1e30f, m1 = -1e30f, l0 = 0.0f, l1 = 0.0f;

        const int qi0 = qt * 128 + r0;
        const int qi1 = qi0 + 8;

        for (int kt = 0; kt < nkt; kt++) {
            if (kt + 1 < nkt) { CP_WAIT1(); } else { CP_WAIT0(); }
            __syncthreads();   // the ONLY barrier per iteration
            const int bf = kt % 3;
            const float* Ks = sm + bf * KS_BUF;
            const float* Vs = sm + OFF_VS + bf * VS_BUF;

            // S = Q @ K^T : one LDS.128 feeds two k8 MMAs.
            float sa[8][4];
#pragma unroll
            for (int nt = 0; nt < 8; nt++)
#pragma unroll
                for (int j = 0; j < 4; j++) sa[nt][j] = 0.0f;
#pragma unroll
            for (int kb16 = 0; kb16 < 4; kb16++) {
#pragma unroll
                for (int nt = 0; nt < 8; nt++) {
                    const float4 kk = *(const float4*)(Ks +
                        (nt * 8 + lr) * KS_ST + kb16 * 16 + lc * 4);
                    mma1688(sa[nt], qf[2 * kb16][0], qf[2 * kb16][1],
                            qf[2 * kb16][2], qf[2 * kb16][3], kk.x, kk.y);
                    mma1688(sa[nt], qf[2 * kb16 + 1][0], qf[2 * kb16 + 1][1],
                            qf[2 * kb16 + 1][2], qf[2 * kb16 + 1][3], kk.z, kk.w);
                }
            }

            if (kt >= 2 * qt) {
#pragma unroll
                for (int nt = 0; nt < 8; nt++) {
                    const int kj = kt * 64 + nt * 8 + 2 * lc;
                    if (kj > qi0)     sa[nt][0] = -1e30f;
                    if (kj + 1 > qi0) sa[nt][1] = -1e30f;
                    if (kj > qi1)     sa[nt][2] = -1e30f;
                    if (kj + 1 > qi1) sa[nt][3] = -1e30f;
                }
            }

            // Online softmax (log2 domain).
            float mx0 = sa[0][0], mx1 = sa[0][2];
#pragma unroll
            for (int nt = 0; nt < 8; nt++) {
                mx0 = fmaxf(mx0, fmaxf(sa[nt][0], sa[nt][1]));
                mx1 = fmaxf(mx1, fmaxf(sa[nt][2], sa[nt][3]));
            }
            mx0 = fmaxf(mx0, __shfl_xor_sync(0xffffffffu, mx0, 1));
            mx0 = fmaxf(mx0, __shfl_xor_sync(0xffffffffu, mx0, 2));
            mx1 = fmaxf(mx1, __shfl_xor_sync(0xffffffffu, mx1, 1));
            mx1 = fmaxf(mx1, __shfl_xor_sync(0xffffffffu, mx1, 2));
            const float nm0 = fmaxf(m0, mx0), nm1 = fmaxf(m1, mx1);
            const float cf0 = exp2f(m0 - nm0), cf1 = exp2f(m1 - nm1);
            m0 = nm0; m1 = nm1;
            float rs0 = 0.0f, rs1 = 0.0f;
#pragma unroll
            for (int nt = 0; nt < 8; nt++) {
                float p0 = exp2f(sa[nt][0] - nm0);
                float p1 = exp2f(sa[nt][1] - nm0);
                float p2 = exp2f(sa[nt][2] - nm1);
                float p3 = exp2f(sa[nt][3] - nm1);
                rs0 += p0 + p1; rs1 += p2 + p3;
                sa[nt][0] = f2tf32(p0); sa[nt][1] = f2tf32(p1);
                sa[nt][2] = f2tf32(p2); sa[nt][3] = f2tf32(p3);
            }
            rs0 += __shfl_xor_sync(0xffffffffu, rs0, 1);
            rs0 += __shfl_xor_sync(0xffffffffu, rs0, 2);
            rs1 += __shfl_xor_sync(0xffffffffu, rs1, 1);
            rs1 += __shfl_xor_sync(0xffffffffu, rs1, 2);
            l0 = l0 * cf0 + rs0;
            l1 = l1 * cf1 + rs1;
#pragma unroll
            for (int nt = 0; nt < 8; nt++) {
                oacc[nt][0] *= cf0; oacc[nt][1] *= cf0;
                oacc[nt][2] *= cf1; oacc[nt][3] *= cf1;
            }

            // O += P @ V : P fragments from registers via quad shuffles.
#pragma unroll
            for (int kb16 = 0; kb16 < 4; kb16++) {
                float a0, a1, a2, a3, b0, b1, b2, b3;
                XFORM(sa[2 * kb16],     a0, a1, a2, a3);
                XFORM(sa[2 * kb16 + 1], b0, b1, b2, b3);
#pragma unroll
                for (int nt = 0; nt < 8; nt++) {
                    const float4 vv = *(const float4*)(Vs +
                        kb16 * 1024 + (nt * 8 + lr) * 16 + lc * 4);
                    mma1688(oacc[nt], a0, a1, a2, a3, vv.x, vv.y);
                    mma1688(oacc[nt], b0, b1, b2, b3, vv.z, vv.w);
                }
            }
            // No barrier: triple-buffered K/V, reuse distance 2 iterations.
            if (kt + 2 < nkt) stage_kv(kt + 2);
        }

        // Normalize; write packed bf16x2 hi/lo (feeds gemm_o).
        const float inv0 = 1.0f / l0, inv1 = 1.0f / l1;
        const size_t row0 = (size_t)(tb + qt * 128 + r0);
        const int colp = h * 32 + lc;
#pragma unroll
        for (int nt = 0; nt < 8; nt++) {
            float v0 = oacc[nt][0] * inv0, v1 = oacc[nt][1] * inv0;
            float v2 = oacc[nt][2] * inv1, v3 = oacc[nt][3] * inv1;
            __nv_bfloat16 h0 = __float2bfloat16_rn(v0);
            __nv_bfloat16 h1 = __float2bfloat16_rn(v1);
            __nv_bfloat16 h2 = __float2bfloat16_rn(v2);
            __nv_bfloat16 h3 = __float2bfloat16_rn(v3);
            const size_t o0 = row0 * KH2 + colp + nt * 4;
            const size_t o1 = (row0 + 8) * KH2 + colp + nt * 4;
            g_Oh[o0] = packbf(h0, h1);
            g_Ol[o0] = packbf(__float2bfloat16_rn(v0 - __bfloat162float(h0)),
                              __float2bfloat16_rn(v1 - __bfloat162float(h1)));
            g_Oh[o1] = packbf(h2, h3);
            g_Ol[o1] = packbf(__float2bfloat16_rn(v2 - __bfloat162float(h2)),
                              __float2bfloat16_rn(v3 - __bfloat162float(h3)));
        }
    }
}

// ---------------------------------------------------------------------------
extern "C" void kernel_launch(void* const* d_in, const int* in_sizes, int n_in,
                              void* d_out, int out_size)
{
    const float* x  = (const float*)d_in[0];
    const float* Wq = (const float*)d_in[1];
    const float* bq = (const float*)d_in[2];
    const float* Wk = (const float*)d_in[3];
    const float* bk = (const float*)d_in[4];
    const float* Wv = (const float*)d_in[5];
    const float* bv = (const float*)d_in[6];
    const float* Wo = (const float*)d_in[7];
    const float* bo = (const float*)d_in[8];
    float* out = (float*)d_out;

    float *Qp, *Kp, *Vp;
    uint32_t *xh, *xl;
    cudaGetSymbolAddress((void**)&Qp, g_Q);
    cudaGetSymbolAddress((void**)&Kp, g_Kp);
    cudaGetSymbolAddress((void**)&Vp, g_Vp);
    cudaGetSymbolAddress((void**)&xh, g_xh);
    cudaGetSymbolAddress((void**)&xl, g_xl);

    cudaFuncSetAttribute(gemm_qkv, cudaFuncAttributeMaxDynamicSharedMemorySize, GEMM_SMEM);
    cudaFuncSetAttribute(gemm_o,   cudaFuncAttributeMaxDynamicSharedMemorySize, GEMM_SMEM);
    cudaFuncSetAttribute(attn_mma, cudaFuncAttributeMaxDynamicSharedMemorySize, ATTN_SMEM);

    // One-shot conversions (+ job counter reset inside conv_pack).
    conv_pack<<<(BT * D_MODEL / 4 + 255) / 256, 256>>>(x, xh, xl, BT * D_MODEL / 4);
    conv_wT_all<<<dim3(D_MODEL / 32, D_MODEL / 32, 4), dim3(32, 8)>>>(Wq, Wk, Wv, Wo);

    // Fused QKV projection (Q tf32+scaled; K tf32 d-quads; V tf32 t-quads).
    gemm_qkv<<<dim3((D_MODEL + 2 * KV_DIM) / 128, BT / 128), 256, GEMM_SMEM>>>(
        bq, bk, bv, Qp, Kp, Vp);

    // Causal GQA attention (persistent CTAs, dynamic job scheduling).
    attn_mma<<<304, 256, ATTN_SMEM>>>();

    // Output projection.
    gemm_o<<<dim3(D_MODEL / 128, BT / 128), 256, GEMM_SMEM>>>(bo, out);
}